// round 8
// baseline (speedup 1.0000x reference)
#include <cuda_runtime.h>
#include <cuda_bf16.h>
#include <math.h>

#define B_  8
#define L_  1024
#define D_  512
#define H_  8
#define DH_ 64
#define M_  (B_*L_)     // 8192
#define BH_ (B_*H_)     // 64

// Scratch (device globals: allocation-free kernel_launch per harness rules)
__device__ __align__(16) float g_Q[BH_*L_*DH_];   // tf32-rounded, 0.125*log2e-scaled
__device__ __align__(16) float g_K[BH_*L_*DH_];
__device__ __align__(16) float g_Vt[BH_*DH_*L_];  // V transposed: (b,h,dh,l)
__device__ __align__(16) float g_Ctx[M_*D_];      // tf32-rounded, (b,l,D)
__device__ __align__(16) float g_x [M_*D_];       // tf32-rounded inputs
__device__ __align__(16) float g_Wq[D_*D_];
__device__ __align__(16) float g_Wk[D_*D_];
__device__ __align__(16) float g_Wv[D_*D_];
__device__ __align__(16) float g_Wo[D_*D_];
__device__ __align__(16) float g_We[L_*DH_];
__device__ __align__(16) __nv_bfloat16 g_B[(size_t)BH_*L_*L_];  // bias[bh][l][s], log2 domain

// ---------------------------------------------------------------------------
// helpers
// ---------------------------------------------------------------------------
__device__ __forceinline__ unsigned f2tf(float f) {
    unsigned u; asm("cvt.rna.tf32.f32 %0, %1;" : "=r"(u) : "f"(f)); return u;
}
__device__ __forceinline__ float ex2_(float f) {
    float r; asm("ex2.approx.f32 %0, %1;" : "=f"(r) : "f"(f)); return r;
}
__device__ __forceinline__ void mma8(float* c,
    unsigned a0, unsigned a1, unsigned a2, unsigned a3,
    unsigned b0, unsigned b1)
{
    asm volatile(
        "mma.sync.aligned.m16n8k8.row.col.f32.tf32.tf32.f32 "
        "{%0,%1,%2,%3},{%4,%5,%6,%7},{%8,%9},{%0,%1,%2,%3};"
        : "+f"(c[0]), "+f"(c[1]), "+f"(c[2]), "+f"(c[3])
        : "r"(a0), "r"(a1), "r"(a2), "r"(a3), "r"(b0), "r"(b1));
}
__device__ __forceinline__ void ldsm4(unsigned& r0, unsigned& r1,
                                      unsigned& r2, unsigned& r3, unsigned addr)
{
    asm volatile("ldmatrix.sync.aligned.m8n8.x4.shared.b16 {%0,%1,%2,%3}, [%4];"
        : "=r"(r0), "=r"(r1), "=r"(r2), "=r"(r3) : "r"(addr));
}
__device__ __forceinline__ unsigned scvta(const void* p) {
    return (unsigned)__cvta_generic_to_shared(p);
}
__device__ __forceinline__ void cpa16(unsigned dst, const void* src) {
    asm volatile("cp.async.cg.shared.global [%0], [%1], 16;" :: "r"(dst), "l"(src));
}
__device__ __forceinline__ void cpa_commit() {
    asm volatile("cp.async.commit_group;");
}
template<int N> __device__ __forceinline__ void cpa_wait() {
    asm volatile("cp.async.wait_group %0;" :: "n"(N));
}

// ---------------------------------------------------------------------------
// Prep kernels (3 launches)
// ---------------------------------------------------------------------------
__global__ void __launch_bounds__(256) round_kernel(
    const float* __restrict__ s, float* __restrict__ d, int n)
{
    int i = (blockIdx.x * 256 + threadIdx.x) * 4;
    if (i >= n) return;
    float4 v = *(const float4*)(s + i);
    *(uint4*)(d + i) = make_uint4(f2tf(v.x), f2tf(v.y), f2tf(v.z), f2tf(v.w));
}

__global__ void __launch_bounds__(256) round4_kernel(
    const float* __restrict__ a, const float* __restrict__ b,
    const float* __restrict__ c, const float* __restrict__ d)
{
    const float* s = (blockIdx.z == 0) ? a : (blockIdx.z == 1) ? b :
                     (blockIdx.z == 2) ? c : d;
    float* dst     = (blockIdx.z == 0) ? g_Wq : (blockIdx.z == 1) ? g_Wk :
                     (blockIdx.z == 2) ? g_Wv : g_Wo;
    int i = (blockIdx.x * 256 + threadIdx.x) * 4;
    if (i >= D_*D_) return;
    float4 v = *(const float4*)(s + i);
    *(uint4*)(dst + i) = make_uint4(f2tf(v.x), f2tf(v.y), f2tf(v.z), f2tf(v.w));
}

// ---------------------------------------------------------------------------
// Dense GEMM body (K=512): C(128x128) = A * W^T.
// 3-stage cp.async pipeline, ONE __syncthreads per k-iter, ldmatrix frags.
// ---------------------------------------------------------------------------
__device__ __forceinline__ void gemm_body(
    const float* __restrict__ A, const float* __restrict__ W,
    int mBase, int nBase, unsigned* As, unsigned* Bs, float C[2][8][4])
{
    const int t = threadIdx.x, lane = t & 31, warp = t >> 5;
    const int wm = warp >> 1, wn = warp & 1;
    const int lr = t >> 3, lc = (t & 7) * 4;
    const int BUF = 128 * 36;

    unsigned as_a = scvta(As + lr*36 + lc);
    unsigned bs_a = scvta(Bs + lr*36 + lc);

    auto stage = [&](int buf, int k0) {
        #pragma unroll
        for (int i = 0; i < 4; i++) {
            unsigned off = (unsigned)(buf*BUF + i*32*36) * 4u;
            cpa16(as_a + off, A + (size_t)(mBase + lr + 32*i) * D_ + k0 + lc);
            cpa16(bs_a + off, W + (size_t)(nBase + lr + 32*i) * D_ + k0 + lc);
        }
        cpa_commit();
    };

    const int lr8 = lane & 7;
    const int arow = wm*32 + lr8 + ((lane & 8) ? 8 : 0);
    const int acol = (lane & 16) ? 4 : 0;
    unsigned aAddr = scvta(As) + (unsigned)((arow*36 + acol) * 4);
    const int brow = wn*64 + lr8 + ((lane & 16) ? 8 : 0);
    const int bcol = (lane & 8) ? 4 : 0;
    unsigned bAddr = scvta(Bs) + (unsigned)((brow*36 + bcol) * 4);

    stage(0, 0);
    stage(1, 32);
    int cb = 0, nb = 2, nk = 64;
    for (int it = 0; it < 16; it++) {
        cpa_wait<1>();
        __syncthreads();
        if (it + 2 < 16) {
            stage(nb, nk);
            nk += 32;
            nb = (nb == 2) ? 0 : nb + 1;
        }
        const unsigned bo = (unsigned)(cb * BUF * 4);
        #pragma unroll
        for (int kk = 0; kk < 32; kk += 8) {
            unsigned a[2][4];
            #pragma unroll
            for (int mi = 0; mi < 2; mi++)
                ldsm4(a[mi][0], a[mi][1], a[mi][2], a[mi][3],
                      aAddr + bo + (unsigned)((mi*16*36 + kk) * 4));
            #pragma unroll
            for (int jp = 0; jp < 4; jp++) {
                unsigned b0, b1, b2, b3;
                ldsm4(b0, b1, b2, b3, bAddr + bo + (unsigned)((jp*16*36 + kk) * 4));
                mma8(C[0][jp*2],   a[0][0], a[0][1], a[0][2], a[0][3], b0, b1);
                mma8(C[0][jp*2+1], a[0][0], a[0][1], a[0][2], a[0][3], b2, b3);
                mma8(C[1][jp*2],   a[1][0], a[1][1], a[1][2], a[1][3], b0, b1);
                mma8(C[1][jp*2+1], a[1][0], a[1][1], a[1][2], a[1][3], b2, b3);
            }
        }
        cb = (cb == 2) ? 0 : cb + 1;
    }
}

// ---------------------------------------------------------------------------
// Kernel: QKV projections. Q scaled by 0.125*log2(e); V stored transposed.
// ---------------------------------------------------------------------------
__global__ void __launch_bounds__(256, 2) qkv_kernel()
{
    extern __shared__ unsigned smq[];
    unsigned* As = smq;
    unsigned* Bs = smq + 3*128*36;
    const float* W = (blockIdx.z == 0) ? g_Wq : (blockIdx.z == 1) ? g_Wk : g_Wv;
    const float scale = (blockIdx.z == 0) ? 0.125f * 1.4426950408889634f : 1.0f;
    const int mBase = blockIdx.x * 128, nBase = blockIdx.y * 128;
    float C[2][8][4] = {};
    gemm_body(g_x, W, mBase, nBase, As, Bs, C);

    const int t = threadIdx.x, lane = t & 31, warp = t >> 5;
    const int g = lane >> 2, tg = lane & 3;
    const int wm = warp >> 1, wn = warp & 1;

    if (blockIdx.z == 2) {
        #pragma unroll
        for (int mi = 0; mi < 2; mi++) {
            #pragma unroll
            for (int j = 0; j < 8; j++) {
                int n = nBase + wn*64 + j*8 + 2*tg;
                int h = n >> 6, dh = n & 63;
                #pragma unroll
                for (int hh = 0; hh < 2; hh++) {
                    int m = mBase + wm*32 + mi*16 + g + 8*hh;
                    int b = m >> 10, l = m & (L_-1);
                    float* base = g_Vt + ((size_t)((b*H_+h)*DH_ + dh))*L_ + l;
                    base[0]  = __uint_as_float(f2tf(C[mi][j][hh*2]));
                    base[L_] = __uint_as_float(f2tf(C[mi][j][hh*2+1]));
                }
            }
        }
    } else {
        float* dst = (blockIdx.z == 0) ? g_Q : g_K;
        #pragma unroll
        for (int mi = 0; mi < 2; mi++) {
            #pragma unroll
            for (int j = 0; j < 8; j++) {
                int n = nBase + wn*64 + j*8 + 2*tg;
                int h = n >> 6, dh = n & 63;
                #pragma unroll
                for (int hh = 0; hh < 2; hh++) {
                    int m = mBase + wm*32 + mi*16 + g + 8*hh;
                    int b = m >> 10, l = m & (L_-1);
                    float2 v = make_float2(__uint_as_float(f2tf(C[mi][j][hh*2]*scale)),
                                           __uint_as_float(f2tf(C[mi][j][hh*2+1]*scale)));
                    *(float2*)(dst + ((size_t)((b*H_+h)*L_ + l))*DH_ + dh) = v;
                }
            }
        }
    }
}

// ---------------------------------------------------------------------------
// Kernel: bias matrix. Computes Rval(l,e) = Qscaled[l,:].We[e,:] then scatters
// to B[l][s] for s = l +- (1023-e): each (l,s) written exactly once, coalesced.
// ---------------------------------------------------------------------------
__global__ void __launch_bounds__(256, 2) rel_kernel()
{
    extern __shared__ unsigned smr[];
    unsigned* As = smr;             // 128 x 68
    unsigned* Bs = smr + 128*68;
    const int bh = blockIdx.z;
    const int mBase = blockIdx.x * 128, nBase = blockIdx.y * 128;
    const float* A = g_Q + (size_t)bh * L_ * DH_;
    const float* Wb = g_We;

    const int t = threadIdx.x, lane = t & 31, warp = t >> 5;
    const int wm = warp >> 1, wn = warp & 1;
    const int lr = t >> 4, lc = (t & 15) * 4;

    unsigned as_a = scvta(As + lr*68 + lc);
    unsigned bs_a = scvta(Bs + lr*68 + lc);
    #pragma unroll
    for (int i = 0; i < 8; i++) {
        unsigned off = (unsigned)(i*16*68) * 4u;
        cpa16(as_a + off, A  + (size_t)(mBase + lr + 16*i) * DH_ + lc);
        cpa16(bs_a + off, Wb + (size_t)(nBase + lr + 16*i) * DH_ + lc);
    }
    cpa_commit(); cpa_wait<0>();
    __syncthreads();

    const int lr8 = lane & 7;
    unsigned aAddr = scvta(As) + (unsigned)(((wm*32 + lr8 + ((lane&8)?8:0))*68 + ((lane&16)?4:0)) * 4);
    unsigned bAddr = scvta(Bs) + (unsigned)(((wn*64 + lr8 + ((lane&16)?8:0))*68 + ((lane&8)?4:0)) * 4);

    float C[2][8][4] = {};
    #pragma unroll
    for (int kk = 0; kk < 64; kk += 8) {
        unsigned a[2][4];
        #pragma unroll
        for (int mi = 0; mi < 2; mi++)
            ldsm4(a[mi][0], a[mi][1], a[mi][2], a[mi][3],
                  aAddr + (unsigned)((mi*16*68 + kk) * 4));
        #pragma unroll
        for (int jp = 0; jp < 4; jp++) {
            unsigned b0, b1, b2, b3;
            ldsm4(b0, b1, b2, b3, bAddr + (unsigned)((jp*16*68 + kk) * 4));
            mma8(C[0][jp*2],   a[0][0], a[0][1], a[0][2], a[0][3], b0, b1);
            mma8(C[0][jp*2+1], a[0][0], a[0][1], a[0][2], a[0][3], b2, b3);
            mma8(C[1][jp*2],   a[1][0], a[1][1], a[1][2], a[1][3], b0, b1);
            mma8(C[1][jp*2+1], a[1][0], a[1][1], a[1][2], a[1][3], b2, b3);
        }
    }

    const int g = lane >> 2, tg = lane & 3;
    __nv_bfloat16* Bb = g_B + (size_t)bh * L_ * L_;
    #pragma unroll
    for (int mi = 0; mi < 2; mi++) {
        #pragma unroll
        for (int j = 0; j < 8; j++) {
            int e0 = nBase + wn*64 + j*8 + 2*tg;
            #pragma unroll
            for (int hh = 0; hh < 2; hh++) {
                int m = mBase + wm*32 + mi*16 + g + 8*hh;
                #pragma unroll
                for (int q = 0; q < 2; q++) {
                    int e = e0 + q;
                    __nv_bfloat16 hv = __float2bfloat16_rn(C[mi][j][hh*2 + q]);
                    int s1 = m - 1023 + e;              // s1 <= m < 1024
                    int s2 = m + 1023 - e;              // s2 >= m >= 0
                    if (s1 >= 0)  Bb[(size_t)m*L_ + s1] = hv;
                    if (s2 < L_)  Bb[(size_t)m*L_ + s2] = hv;
                }
            }
        }
    }
}

// ---------------------------------------------------------------------------
// Kernel: flash attention. Bias tile cp.async-staged (rectangular B[l][s]),
// sf init from smem (LDS.u32, latency hidden). ldmatrix frags, no-max log2
// softmax, P in registers via C->A quad shuffles, V pre-transposed.
// ---------------------------------------------------------------------------
__global__ void __launch_bounds__(128, 3) attn_kernel()
{
    extern __shared__ unsigned sma[];
    unsigned* Qs = sma;             // 64 x 68  [l][dh]
    unsigned* Ks = Qs + 64*68;      // [s][dh]
    unsigned* Vt = Ks + 64*68;      // [dh][s]
    unsigned* Bt = Vt + 64*68;      // 64 x 36 bias tile (bf16x2 words)

    const int bh = blockIdx.y, lBase = blockIdx.x * 64;
    const float* __restrict__ Qg  = g_Q  + (size_t)bh * L_ * DH_;
    const float* __restrict__ Kg  = g_K  + (size_t)bh * L_ * DH_;
    const float* __restrict__ Vtg = g_Vt + (size_t)bh * DH_ * L_;
    const __nv_bfloat16* __restrict__ Bg = g_B + ((size_t)bh << 20);

    const int t = threadIdx.x, lane = t & 31, warp = t >> 5;
    const int g = lane >> 2, tg = lane & 3;
    const int rA = warp*16 + g;

    // K/V/Q staging: row (t&63), chunk half (t>>6)*8; pitch 272B
    const int srow = t & 63, scb = (t >> 6) * 8;
    unsigned q_a = scvta(Qs) + (unsigned)(srow*272);
    unsigned k_a = scvta(Ks) + (unsigned)(srow*272);
    unsigned v_a = scvta(Vt) + (unsigned)(srow*272);
    // bias staging: row (t>>1), 4 chunks at (t&1)*4; pitch 144B
    const int brow = t >> 1, bcb = (t & 1) * 4;
    unsigned b_a = scvta(Bt) + (unsigned)(brow*144 + bcb*16);
    const __nv_bfloat16* bsrc0 = Bg + (size_t)(lBase + brow)*L_ + bcb*8;

    {   // stage Q + first K/Vt/bias tiles
        const float* qs = Qg  + (size_t)(lBase + srow)*DH_;
        const float* ks = Kg  + (size_t)srow*DH_;
        const float* vs = Vtg + (size_t)srow*L_;
        #pragma unroll
        for (int i = 0; i < 8; i++) {
            int ci = scb + i;
            cpa16(q_a + ci*16, qs + ci*4);
            cpa16(k_a + ci*16, ks + ci*4);
            cpa16(v_a + ci*16, vs + ci*4);
        }
        #pragma unroll
        for (int i = 0; i < 4; i++)
            cpa16(b_a + i*16, bsrc0 + i*8);
        cpa_commit();
    }

    const int lr8 = lane & 7;
    unsigned aQ = scvta(Qs) +
        (unsigned)(((warp*16 + lr8 + ((lane&8)?8:0))*68 + ((lane&16)?4:0)) * 4);
    const int bRow = lr8 + ((lane&16)?8:0);
    const int bCol = (lane&8)?4:0;
    unsigned bK0 = scvta(Ks) + (unsigned)((bRow*68 + bCol) * 4);
    unsigned bV0 = scvta(Vt) + (unsigned)((bRow*68 + bCol) * 4);

    float lrun0 = 0.f, lrun1 = 0.f;
    float O[8][4] = {};

    for (int sBase = 0; sBase < L_; sBase += 64) {
        cpa_wait<0>();
        __syncthreads();                                    // (1) tiles visible

        // ---- sf init from smem bias tile (bf16x2) ----
        float sf[8][4];
        #pragma unroll
        for (int j = 0; j < 8; j++) {
            unsigned w0 = Bt[rA*36     + 4*j + tg];
            unsigned w1 = Bt[(rA+8)*36 + 4*j + tg];
            float2 f0 = __bfloat1622float2(*(__nv_bfloat162*)&w0);
            float2 f1 = __bfloat1622float2(*(__nv_bfloat162*)&w1);
            sf[j][0] = f0.x; sf[j][1] = f0.y;
            sf[j][2] = f1.x; sf[j][3] = f1.y;
        }

        // ---- S GEMM (accumulates onto bias) ----
        #pragma unroll
        for (int k0 = 0; k0 < 64; k0 += 8) {
            unsigned a0, a1, a2, a3;
            ldsm4(a0, a1, a2, a3, aQ + (unsigned)(k0*4));
            #pragma unroll
            for (int jp = 0; jp < 4; jp++) {
                unsigned b0, b1, b2, b3;
                ldsm4(b0, b1, b2, b3, bK0 + (unsigned)((jp*16*68 + k0) * 4));
                mma8(sf[jp*2],   a0, a1, a2, a3, b0, b1);
                mma8(sf[jp*2+1], a0, a1, a2, a3, b2, b3);
            }
        }

        // ---- fused softmax (no max) + PV per col-block ----
        #pragma unroll
        for (int j2 = 0; j2 < 8; j2++) {
            float p0 = ex2_(sf[j2][0]);
            float p1 = ex2_(sf[j2][1]);
            float p2 = ex2_(sf[j2][2]);
            float p3 = ex2_(sf[j2][3]);
            lrun0 += p0 + p1;
            lrun1 += p2 + p3;

            int ls  = (lane & ~3) | (tg >> 1);
            int ls2 = ls + 2;
            float s00 = __shfl_sync(0xffffffffu, p0, ls);
            float s01 = __shfl_sync(0xffffffffu, p1, ls);
            float s10 = __shfl_sync(0xffffffffu, p2, ls);
            float s11 = __shfl_sync(0xffffffffu, p3, ls);
            float u00 = __shfl_sync(0xffffffffu, p0, ls2);
            float u01 = __shfl_sync(0xffffffffu, p1, ls2);
            float u10 = __shfl_sync(0xffffffffu, p2, ls2);
            float u11 = __shfl_sync(0xffffffffu, p3, ls2);
            bool odd = (tg & 1);
            unsigned a0 = f2tf(odd ? s01 : s00);
            unsigned a1 = f2tf(odd ? s11 : s10);
            unsigned a2 = f2tf(odd ? u01 : u00);
            unsigned a3 = f2tf(odd ? u11 : u10);

            #pragma unroll
            for (int jp = 0; jp < 4; jp++) {
                unsigned b0, b1, b2, b3;
                ldsm4(b0, b1, b2, b3, bV0 + (unsigned)((jp*16*68 + j2*8) * 4));
                mma8(O[jp*2],   a0, a1, a2, a3, b0, b1);
                mma8(O[jp*2+1], a0, a1, a2, a3, b2, b3);
            }
        }
        __syncthreads();                                    // (2) tiles reusable

        if (sBase + 64 < L_) {   // prefetch next K/Vt/bias tiles
            const float* ks = Kg  + (size_t)(sBase + 64 + srow)*DH_;
            const float* vs = Vtg + (size_t)srow*L_ + sBase + 64;
            const __nv_bfloat16* bs = bsrc0 + sBase + 64;
            #pragma unroll
            for (int i = 0; i < 8; i++) {
                int ci = scb + i;
                cpa16(k_a + ci*16, ks + ci*4);
                cpa16(v_a + ci*16, vs + ci*4);
            }
            #pragma unroll
            for (int i = 0; i < 4; i++)
                cpa16(b_a + i*16, bs + i*8);
            cpa_commit();
        }
    }

    // deferred row-sum reduction (quad) + normalize + write ctx
    lrun0 += __shfl_xor_sync(0xffffffffu, lrun0, 1);
    lrun0 += __shfl_xor_sync(0xffffffffu, lrun0, 2);
    lrun1 += __shfl_xor_sync(0xffffffffu, lrun1, 1);
    lrun1 += __shfl_xor_sync(0xffffffffu, lrun1, 2);
    const float i0 = 1.0f / lrun0, i1 = 1.0f / lrun1;
    const int b = bh >> 3, hh = bh & 7;
    #pragma unroll
    for (int j = 0; j < 8; j++) {
        int dh = j*8 + 2*tg;
        size_t base0 = ((size_t)(b*L_ + lBase + rA))*D_ + hh*DH_ + dh;
        size_t base1 = ((size_t)(b*L_ + lBase + rA + 8))*D_ + hh*DH_ + dh;
        *(float2*)(g_Ctx + base0) = make_float2(__uint_as_float(f2tf(O[j][0]*i0)),
                                                __uint_as_float(f2tf(O[j][1]*i0)));
        *(float2*)(g_Ctx + base1) = make_float2(__uint_as_float(f2tf(O[j][2]*i1)),
                                                __uint_as_float(f2tf(O[j][3]*i1)));
    }
}

// ---------------------------------------------------------------------------
// Kernel: out = Ctx @ Wo^T + bo
// ---------------------------------------------------------------------------
__global__ void __launch_bounds__(256, 2) out_kernel(
    const float* __restrict__ bo, float* __restrict__ out)
{
    extern __shared__ unsigned smq[];
    unsigned* As = smq;
    unsigned* Bs = smq + 3*128*36;
    const int mBase = blockIdx.x * 128, nBase = blockIdx.y * 128;
    float C[2][8][4] = {};
    gemm_body(g_Ctx, g_Wo, mBase, nBase, As, Bs, C);

    const int t = threadIdx.x, lane = t & 31, warp = t >> 5;
    const int g = lane >> 2, tg = lane & 3;
    const int wm = warp >> 1, wn = warp & 1;
    #pragma unroll
    for (int mi = 0; mi < 2; mi++) {
        #pragma unroll
        for (int j = 0; j < 8; j++) {
            int n = nBase + wn*64 + j*8 + 2*tg;
            float2 bias = *(const float2*)(bo + n);
            #pragma unroll
            for (int hh = 0; hh < 2; hh++) {
                int m = mBase + wm*32 + mi*16 + g + 8*hh;
                float2 v = make_float2(C[mi][j][hh*2] + bias.x, C[mi][j][hh*2+1] + bias.y);
                *(float2*)(out + (size_t)m*D_ + n) = v;
            }
        }
    }
}

// ---------------------------------------------------------------------------
extern "C" void kernel_launch(void* const* d_in, const int* in_sizes, int n_in,
                              void* d_out, int out_size)
{
    const float* x  = (const float*)d_in[0];
    const float* Wq = (const float*)d_in[1];
    const float* Wk = (const float*)d_in[2];
    const float* Wv = (const float*)d_in[3];
    const float* We = (const float*)d_in[4];
    const float* Wo = (const float*)d_in[5];
    const float* bo = (const float*)d_in[6];
    float* out = (float*)d_out;

    const int gemm_smem = 2 * 3 * 128 * 36 * (int)sizeof(unsigned);   // 110592
    const int rel_smem  = 2 * 128 * 68 * (int)sizeof(unsigned);       // 69632
    const int attn_smem = (3 * 64 * 68 + 64 * 36) * (int)sizeof(unsigned);  // 61440
    cudaFuncSetAttribute(qkv_kernel,  cudaFuncAttributeMaxDynamicSharedMemorySize, gemm_smem);
    cudaFuncSetAttribute(rel_kernel,  cudaFuncAttributeMaxDynamicSharedMemorySize, rel_smem);
    cudaFuncSetAttribute(attn_kernel, cudaFuncAttributeMaxDynamicSharedMemorySize, attn_smem);
    cudaFuncSetAttribute(out_kernel,  cudaFuncAttributeMaxDynamicSharedMemorySize, gemm_smem);

    float* gx;  cudaGetSymbolAddress((void**)&gx,  g_x);
    float* gwe; cudaGetSymbolAddress((void**)&gwe, g_We);

    round_kernel<<<M_*D_/1024, 256>>>(x, gx, M_*D_);
    round4_kernel<<<dim3(D_*D_/1024, 1, 4), 256>>>(Wq, Wk, Wv, Wo);
    round_kernel<<<L_*DH_/1024, 256>>>(We, gwe, L_*DH_);

    qkv_kernel<<<dim3(M_/128, D_/128, 3), 256, gemm_smem>>>();
    rel_kernel<<<dim3(L_/128, L_/128, BH_), 256, rel_smem>>>();
    attn_kernel<<<dim3(L_/64, BH_), 128, attn_smem>>>();
    out_kernel<<<dim3(M_/128, D_/128), 256, gemm_smem>>>(bo, out);
}

// round 9
// speedup vs baseline: 1.5141x; 1.5141x over previous
#include <cuda_runtime.h>
#include <cuda_bf16.h>
#include <cuda_fp16.h>
#include <math.h>

#define B_  8
#define L_  1024
#define D_  512
#define H_  8
#define DH_ 64
#define M_  (B_*L_)     // 8192
#define BH_ (B_*H_)     // 64

// Scratch (device globals: allocation-free kernel_launch per harness rules)
__device__ __align__(16) float g_Q[BH_*L_*DH_];   // tf32-rounded, 0.125*log2e-scaled
__device__ __align__(16) float g_K[BH_*L_*DH_];
__device__ __align__(16) __half g_Vh[BH_*L_*DH_]; // V fp16, (b,h,l,dh)
__device__ __align__(16) float g_Ctx[M_*D_];      // tf32-rounded, (b,l,D)
__device__ __align__(16) float g_x [M_*D_];       // tf32-rounded inputs
__device__ __align__(16) float g_Wq[D_*D_];
__device__ __align__(16) float g_Wk[D_*D_];
__device__ __align__(16) float g_Wv[D_*D_];
__device__ __align__(16) float g_Wo[D_*D_];
__device__ __align__(16) float g_We[L_*DH_];
__device__ __align__(16) __nv_bfloat16 g_R[(size_t)BH_*L_*L_];  // bias (log2 domain)

// ---------------------------------------------------------------------------
// helpers
// ---------------------------------------------------------------------------
__device__ __forceinline__ unsigned f2tf(float f) {
    unsigned u; asm("cvt.rna.tf32.f32 %0, %1;" : "=r"(u) : "f"(f)); return u;
}
__device__ __forceinline__ void mma8(float* c,
    unsigned a0, unsigned a1, unsigned a2, unsigned a3,
    unsigned b0, unsigned b1)
{
    asm volatile(
        "mma.sync.aligned.m16n8k8.row.col.f32.tf32.tf32.f32 "
        "{%0,%1,%2,%3},{%4,%5,%6,%7},{%8,%9},{%0,%1,%2,%3};"
        : "+f"(c[0]), "+f"(c[1]), "+f"(c[2]), "+f"(c[3])
        : "r"(a0), "r"(a1), "r"(a2), "r"(a3), "r"(b0), "r"(b1));
}
__device__ __forceinline__ void mma16h(float* c,
    unsigned a0, unsigned a1, unsigned a2, unsigned a3,
    unsigned b0, unsigned b1)
{
    asm volatile(
        "mma.sync.aligned.m16n8k16.row.col.f32.f16.f16.f32 "
        "{%0,%1,%2,%3},{%4,%5,%6,%7},{%8,%9},{%0,%1,%2,%3};"
        : "+f"(c[0]), "+f"(c[1]), "+f"(c[2]), "+f"(c[3])
        : "r"(a0), "r"(a1), "r"(a2), "r"(a3), "r"(b0), "r"(b1));
}
__device__ __forceinline__ void ldsm4(unsigned& r0, unsigned& r1,
                                      unsigned& r2, unsigned& r3, unsigned addr)
{
    asm volatile("ldmatrix.sync.aligned.m8n8.x4.shared.b16 {%0,%1,%2,%3}, [%4];"
        : "=r"(r0), "=r"(r1), "=r"(r2), "=r"(r3) : "r"(addr));
}
__device__ __forceinline__ void ldsm4t(unsigned& r0, unsigned& r1,
                                       unsigned& r2, unsigned& r3, unsigned addr)
{
    asm volatile("ldmatrix.sync.aligned.m8n8.x4.trans.shared.b16 {%0,%1,%2,%3}, [%4];"
        : "=r"(r0), "=r"(r1), "=r"(r2), "=r"(r3) : "r"(addr));
}
// pack two floats to f16x2 and apply 2^x elementwise (1 MUFU op for 2 values)
__device__ __forceinline__ unsigned ex2h2(float lo, float hi) {
    unsigned p;
    asm("cvt.rn.f16x2.f32 %0, %1, %2;" : "=r"(p) : "f"(hi), "f"(lo));
    asm("ex2.approx.f16x2 %0, %0;" : "+r"(p));
    return p;
}
__device__ __forceinline__ unsigned scvta(const void* p) {
    return (unsigned)__cvta_generic_to_shared(p);
}
__device__ __forceinline__ void cpa16(unsigned dst, const void* src) {
    asm volatile("cp.async.cg.shared.global [%0], [%1], 16;" :: "r"(dst), "l"(src));
}
__device__ __forceinline__ void cpa_commit() {
    asm volatile("cp.async.commit_group;");
}
template<int N> __device__ __forceinline__ void cpa_wait() {
    asm volatile("cp.async.wait_group %0;" :: "n"(N));
}

// ---------------------------------------------------------------------------
// Prep: ONE launch rounding all inputs to tf32 (attn becomes launch #4)
// ---------------------------------------------------------------------------
#define XN_ (M_*D_)
#define WN_ (D_*D_)
__global__ void __launch_bounds__(256) prep_kernel(
    const float* __restrict__ x,  const float* __restrict__ Wq,
    const float* __restrict__ Wk, const float* __restrict__ Wv,
    const float* __restrict__ Wo, const float* __restrict__ We)
{
    int i = (blockIdx.x * 256 + threadIdx.x) * 4;
    const float* s; float* d;
    if      (i < XN_)          { s = x  + i;                 d = g_x  + i; }
    else if (i < XN_ + WN_)    { s = Wq + i - XN_;           d = g_Wq + i - XN_; }
    else if (i < XN_ + 2*WN_)  { s = Wk + i - XN_ - WN_;     d = g_Wk + i - XN_ - WN_; }
    else if (i < XN_ + 3*WN_)  { s = Wv + i - XN_ - 2*WN_;   d = g_Wv + i - XN_ - 2*WN_; }
    else if (i < XN_ + 4*WN_)  { s = Wo + i - XN_ - 3*WN_;   d = g_Wo + i - XN_ - 3*WN_; }
    else if (i < XN_ + 4*WN_ + L_*DH_) { s = We + i - XN_ - 4*WN_; d = g_We + i - XN_ - 4*WN_; }
    else return;
    float4 v = *(const float4*)s;
    *(uint4*)d = make_uint4(f2tf(v.x), f2tf(v.y), f2tf(v.z), f2tf(v.w));
}

// ---------------------------------------------------------------------------
// Dense GEMM body (K=512): C(128x128) = A * W^T.
// 3-stage cp.async pipeline, ONE __syncthreads per k-iter, ldmatrix frags.
// ---------------------------------------------------------------------------
__device__ __forceinline__ void gemm_body(
    const float* __restrict__ A, const float* __restrict__ W,
    int mBase, int nBase, unsigned* As, unsigned* Bs, float C[2][8][4])
{
    const int t = threadIdx.x, lane = t & 31, warp = t >> 5;
    const int wm = warp >> 1, wn = warp & 1;
    const int lr = t >> 3, lc = (t & 7) * 4;
    const int BUF = 128 * 36;

    unsigned as_a = scvta(As + lr*36 + lc);
    unsigned bs_a = scvta(Bs + lr*36 + lc);

    auto stage = [&](int buf, int k0) {
        #pragma unroll
        for (int i = 0; i < 4; i++) {
            unsigned off = (unsigned)(buf*BUF + i*32*36) * 4u;
            cpa16(as_a + off, A + (size_t)(mBase + lr + 32*i) * D_ + k0 + lc);
            cpa16(bs_a + off, W + (size_t)(nBase + lr + 32*i) * D_ + k0 + lc);
        }
        cpa_commit();
    };

    const int lr8 = lane & 7;
    const int arow = wm*32 + lr8 + ((lane & 8) ? 8 : 0);
    const int acol = (lane & 16) ? 4 : 0;
    unsigned aAddr = scvta(As) + (unsigned)((arow*36 + acol) * 4);
    const int brow = wn*64 + lr8 + ((lane & 16) ? 8 : 0);
    const int bcol = (lane & 8) ? 4 : 0;
    unsigned bAddr = scvta(Bs) + (unsigned)((brow*36 + bcol) * 4);

    stage(0, 0);
    stage(1, 32);
    int cb = 0, nb = 2, nk = 64;
    for (int it = 0; it < 16; it++) {
        cpa_wait<1>();
        __syncthreads();
        if (it + 2 < 16) {
            stage(nb, nk);
            nk += 32;
            nb = (nb == 2) ? 0 : nb + 1;
        }
        const unsigned bo = (unsigned)(cb * BUF * 4);
        #pragma unroll
        for (int kk = 0; kk < 32; kk += 8) {
            unsigned a[2][4];
            #pragma unroll
            for (int mi = 0; mi < 2; mi++)
                ldsm4(a[mi][0], a[mi][1], a[mi][2], a[mi][3],
                      aAddr + bo + (unsigned)((mi*16*36 + kk) * 4));
            #pragma unroll
            for (int jp = 0; jp < 4; jp++) {
                unsigned b0, b1, b2, b3;
                ldsm4(b0, b1, b2, b3, bAddr + bo + (unsigned)((jp*16*36 + kk) * 4));
                mma8(C[0][jp*2],   a[0][0], a[0][1], a[0][2], a[0][3], b0, b1);
                mma8(C[0][jp*2+1], a[0][0], a[0][1], a[0][2], a[0][3], b2, b3);
                mma8(C[1][jp*2],   a[1][0], a[1][1], a[1][2], a[1][3], b0, b1);
                mma8(C[1][jp*2+1], a[1][0], a[1][1], a[1][2], a[1][3], b2, b3);
            }
        }
        cb = (cb == 2) ? 0 : cb + 1;
    }
}

// ---------------------------------------------------------------------------
// Kernel: QKV projections. Q scaled by 0.125*log2(e); V stored fp16.
// ---------------------------------------------------------------------------
__global__ void __launch_bounds__(256, 2) qkv_kernel()
{
    extern __shared__ unsigned smq[];
    unsigned* As = smq;
    unsigned* Bs = smq + 3*128*36;
    const float* W = (blockIdx.z == 0) ? g_Wq : (blockIdx.z == 1) ? g_Wk : g_Wv;
    const float scale = (blockIdx.z == 0) ? 0.125f * 1.4426950408889634f : 1.0f;
    const int mBase = blockIdx.x * 128, nBase = blockIdx.y * 128;
    float C[2][8][4] = {};
    gemm_body(g_x, W, mBase, nBase, As, Bs, C);

    const int t = threadIdx.x, lane = t & 31, warp = t >> 5;
    const int g = lane >> 2, tg = lane & 3;
    const int wm = warp >> 1, wn = warp & 1;

    if (blockIdx.z == 2) {
        #pragma unroll
        for (int mi = 0; mi < 2; mi++) {
            #pragma unroll
            for (int j = 0; j < 8; j++) {
                int n = nBase + wn*64 + j*8 + 2*tg;
                int h = n >> 6, dh = n & 63;
                #pragma unroll
                for (int hh = 0; hh < 2; hh++) {
                    int m = mBase + wm*32 + mi*16 + g + 8*hh;
                    int b = m >> 10, l = m & (L_-1);
                    __half2 v = __floats2half2_rn(C[mi][j][hh*2], C[mi][j][hh*2+1]);
                    *(__half2*)(g_Vh + ((size_t)((b*H_+h)*L_ + l))*DH_ + dh) = v;
                }
            }
        }
    } else {
        float* dst = (blockIdx.z == 0) ? g_Q : g_K;
        #pragma unroll
        for (int mi = 0; mi < 2; mi++) {
            #pragma unroll
            for (int j = 0; j < 8; j++) {
                int n = nBase + wn*64 + j*8 + 2*tg;
                int h = n >> 6, dh = n & 63;
                #pragma unroll
                for (int hh = 0; hh < 2; hh++) {
                    int m = mBase + wm*32 + mi*16 + g + 8*hh;
                    int b = m >> 10, l = m & (L_-1);
                    float2 v = make_float2(__uint_as_float(f2tf(C[mi][j][hh*2]*scale)),
                                           __uint_as_float(f2tf(C[mi][j][hh*2+1]*scale)));
                    *(float2*)(dst + ((size_t)((b*H_+h)*L_ + l))*DH_ + dh) = v;
                }
            }
        }
    }
}

// ---------------------------------------------------------------------------
// Kernel: R[bh][l][e] = Qscaled[bh,l,:] . We[e,:]  (K=64), bf16 output
// ---------------------------------------------------------------------------
__global__ void __launch_bounds__(256, 2) rel_kernel()
{
    extern __shared__ unsigned smr[];
    unsigned* As = smr;             // 128 x 68
    unsigned* Bs = smr + 128*68;
    const int bh = blockIdx.z;
    const int mBase = blockIdx.x * 128, nBase = blockIdx.y * 128;
    const float* A = g_Q + (size_t)bh * L_ * DH_;
    const float* Wb = g_We;

    const int t = threadIdx.x, lane = t & 31, warp = t >> 5;
    const int wm = warp >> 1, wn = warp & 1;
    const int lr = t >> 4, lc = (t & 15) * 4;

    unsigned as_a = scvta(As + lr*68 + lc);
    unsigned bs_a = scvta(Bs + lr*68 + lc);
    #pragma unroll
    for (int i = 0; i < 8; i++) {
        unsigned off = (unsigned)(i*16*68) * 4u;
        cpa16(as_a + off, A  + (size_t)(mBase + lr + 16*i) * DH_ + lc);
        cpa16(bs_a + off, Wb + (size_t)(nBase + lr + 16*i) * DH_ + lc);
    }
    cpa_commit(); cpa_wait<0>();
    __syncthreads();

    const int lr8 = lane & 7;
    unsigned aAddr = scvta(As) + (unsigned)(((wm*32 + lr8 + ((lane&8)?8:0))*68 + ((lane&16)?4:0)) * 4);
    unsigned bAddr = scvta(Bs) + (unsigned)(((wn*64 + lr8 + ((lane&16)?8:0))*68 + ((lane&8)?4:0)) * 4);

    float C[2][8][4] = {};
    #pragma unroll
    for (int kk = 0; kk < 64; kk += 8) {
        unsigned a[2][4];
        #pragma unroll
        for (int mi = 0; mi < 2; mi++)
            ldsm4(a[mi][0], a[mi][1], a[mi][2], a[mi][3],
                  aAddr + (unsigned)((mi*16*68 + kk) * 4));
        #pragma unroll
        for (int jp = 0; jp < 4; jp++) {
            unsigned b0, b1, b2, b3;
            ldsm4(b0, b1, b2, b3, bAddr + (unsigned)((jp*16*68 + kk) * 4));
            mma8(C[0][jp*2],   a[0][0], a[0][1], a[0][2], a[0][3], b0, b1);
            mma8(C[0][jp*2+1], a[0][0], a[0][1], a[0][2], a[0][3], b2, b3);
            mma8(C[1][jp*2],   a[1][0], a[1][1], a[1][2], a[1][3], b0, b1);
            mma8(C[1][jp*2+1], a[1][0], a[1][1], a[1][2], a[1][3], b2, b3);
        }
    }

    const int g = lane >> 2, tg = lane & 3;
    __nv_bfloat16* Rb = g_R + (size_t)bh * L_ * L_;
    #pragma unroll
    for (int mi = 0; mi < 2; mi++) {
        #pragma unroll
        for (int j = 0; j < 8; j++) {
            int n = nBase + wn*64 + j*8 + 2*tg;
            #pragma unroll
            for (int hh = 0; hh < 2; hh++) {
                int m = mBase + wm*32 + mi*16 + g + 8*hh;
                __nv_bfloat162 v = make_bfloat162(
                    __float2bfloat16_rn(C[mi][j][hh*2]),
                    __float2bfloat16_rn(C[mi][j][hh*2+1]));
                *(__nv_bfloat162*)(Rb + (size_t)m*L_ + n) = v;
            }
        }
    }
}

// ---------------------------------------------------------------------------
// Kernel: flash attention. tf32 S GEMM (bias-init via prefetched LDG gather),
// fp16 softmax tail: ex2.approx.f16x2 (half the MUFU ops), C->A frag by pure
// packing (ZERO shuffles), fp16 PV mma (m16n8k16, half the mma/ldsm), row
// sums via ones-column mma (fp32, on tensor core).
// ---------------------------------------------------------------------------
__global__ void __launch_bounds__(128, 4) attn_kernel()
{
    extern __shared__ unsigned sma[];
    unsigned* Qs = sma;             // 64 x 68 u32 [l][dh]
    unsigned* Ks = Qs + 64*68;      // [s][dh]
    __half*   Vh = (__half*)(Ks + 64*68);   // 64 x 72 fp16 [s][dh]

    const int bh = blockIdx.y, lBase = blockIdx.x * 64;
    const float*  __restrict__ Qg  = g_Q  + (size_t)bh * L_ * DH_;
    const float*  __restrict__ Kg  = g_K  + (size_t)bh * L_ * DH_;
    const __half* __restrict__ Vg  = g_Vh + (size_t)bh * L_ * DH_;
    const __nv_bfloat16* __restrict__ Rg = g_R + ((size_t)bh << 20);

    const int t = threadIdx.x, lane = t & 31, warp = t >> 5;
    const int g = lane >> 2, tg = lane & 3;
    const int rA = warp*16 + g;

    // Q/K staging: row (t&63), chunk half (t>>6)*8; pitch 272B
    const int srow = t & 63, scb = (t >> 6) * 8;
    unsigned q_a = scvta(Qs) + (unsigned)(srow*272);
    unsigned k_a = scvta(Ks) + (unsigned)(srow*272);
    // V staging: row 128B = 8 chunks; 2 threads/row, 4 chunks each; pitch 144B
    const int vcb = (t >> 6) * 4;
    unsigned v_a = scvta(Vh) + (unsigned)(srow*144);

    {   // stage Q + first K/V tiles
        const float*  qs = Qg + (size_t)(lBase + srow)*DH_;
        const float*  ks = Kg + (size_t)srow*DH_;
        const __half* vs = Vg + (size_t)srow*DH_;
        #pragma unroll
        for (int i = 0; i < 8; i++) {
            int ci = scb + i;
            cpa16(q_a + ci*16, qs + ci*4);
            cpa16(k_a + ci*16, ks + ci*4);
        }
        #pragma unroll
        for (int i = 0; i < 4; i++) {
            int ci = vcb + i;
            cpa16(v_a + ci*16, vs + ci*8);
        }
        cpa_commit();
    }

    const int lr8 = lane & 7;
    unsigned aQ = scvta(Qs) +
        (unsigned)(((warp*16 + lr8 + ((lane&8)?8:0))*68 + ((lane&16)?4:0)) * 4);
    unsigned bK0 = scvta(Ks) +
        (unsigned)(((lr8 + ((lane&16)?8:0))*68 + ((lane&8)?4:0)) * 4);
    // V B-frag (trans): row = lane%16 (k), col = (lane/16)*8 (n); halves*2 bytes
    unsigned bV0 = scvta(Vh) +
        (unsigned)(((lane & 15)*72 + (lane >> 4)*8) * 2);

    const unsigned ONES = 0x3C003C00u;   // (1.0h, 1.0h)
    float lsum[4] = {0.f, 0.f, 0.f, 0.f};
    float O[8][4] = {};

    const int lg0 = lBase + rA, lg1 = lg0 + 8;
    const __nv_bfloat16* R0 = Rg + ((size_t)lg0 << 10);
    const __nv_bfloat16* R1 = Rg + ((size_t)lg1 << 10);

    for (int sBase = 0; sBase < L_; sBase += 64) {
        // ---- bias gather -> S accumulator init (prefetched before wait) ----
        float sf[8][4];
        #pragma unroll
        for (int j = 0; j < 8; j++) {
            int c0 = sBase + j*8 + 2*tg;
            #pragma unroll
            for (int q = 0; q < 4; q++) {
                int col = c0 + (q & 1);
                int lg  = (q < 2) ? lg0 : lg1;
                int d   = lg - col; int ad = d < 0 ? -d : d;
                sf[j][q] = __bfloat162float(__ldg(((q < 2) ? R0 : R1) + (L_-1) - ad));
            }
        }

        cpa_wait<0>();
        __syncthreads();                                    // (1) tiles visible

        // ---- S GEMM (tf32, accumulates onto bias) ----
        #pragma unroll
        for (int k0 = 0; k0 < 64; k0 += 8) {
            unsigned a0, a1, a2, a3;
            ldsm4(a0, a1, a2, a3, aQ + (unsigned)(k0*4));
            #pragma unroll
            for (int jp = 0; jp < 4; jp++) {
                unsigned b0, b1, b2, b3;
                ldsm4(b0, b1, b2, b3, bK0 + (unsigned)((jp*16*68 + k0) * 4));
                mma8(sf[jp*2],   a0, a1, a2, a3, b0, b1);
                mma8(sf[jp*2+1], a0, a1, a2, a3, b2, b3);
            }
        }

        // ---- fp16 softmax tail + PV (k16 slices) ----
        #pragma unroll
        for (int j2 = 0; j2 < 4; j2++) {
            const int jb0 = 2*j2, jb1 = 2*j2 + 1;
            // pack C-frag pairs -> fp16 A-frag directly (no shuffles)
            unsigned a0 = ex2h2(sf[jb0][0], sf[jb0][1]);   // row g,   k 2tg..2tg+1
            unsigned a1 = ex2h2(sf[jb0][2], sf[jb0][3]);   // row g+8
            unsigned a2 = ex2h2(sf[jb1][0], sf[jb1][1]);   // row g,   k 2tg+8..9
            unsigned a3 = ex2h2(sf[jb1][2], sf[jb1][3]);   // row g+8
            // row sums on the tensor core (B = ones)
            mma16h(lsum, a0, a1, a2, a3, ONES, ONES);
            // PV: O += P(k16) @ V(k16 x 64)
            #pragma unroll
            for (int jp = 0; jp < 4; jp++) {
                unsigned b0, b1, b2, b3;
                ldsm4t(b0, b1, b2, b3,
                       bV0 + (unsigned)((j2*16*72 + jp*16) * 2));
                mma16h(O[jp*2],   a0, a1, a2, a3, b0, b1);
                mma16h(O[jp*2+1], a0, a1, a2, a3, b2, b3);
            }
        }
        __syncthreads();                                    // (2) tiles reusable

        if (sBase + 64 < L_) {   // prefetch next K/V tiles
            const float*  ks = Kg + (size_t)(sBase + 64 + srow)*DH_;
            const __half* vs = Vg + (size_t)(sBase + 64 + srow)*DH_;
            #pragma unroll
            for (int i = 0; i < 8; i++) {
                int ci = scb + i;
                cpa16(k_a + ci*16, ks + ci*4);
            }
            #pragma unroll
            for (int i = 0; i < 4; i++) {
                int ci = vcb + i;
                cpa16(v_a + ci*16, vs + ci*8);
            }
            cpa_commit();
        }
    }

    // normalize (row sums already complete in lsum) + write ctx
    const float i0 = 1.0f / lsum[0], i1 = 1.0f / lsum[2];
    const int b = bh >> 3, hh = bh & 7;
    #pragma unroll
    for (int j = 0; j < 8; j++) {
        int dh = j*8 + 2*tg;
        size_t base0 = ((size_t)(b*L_ + lBase + rA))*D_ + hh*DH_ + dh;
        size_t base1 = ((size_t)(b*L_ + lBase + rA + 8))*D_ + hh*DH_ + dh;
        *(float2*)(g_Ctx + base0) = make_float2(__uint_as_float(f2tf(O[j][0]*i0)),
                                                __uint_as_float(f2tf(O[j][1]*i0)));
        *(float2*)(g_Ctx + base1) = make_float2(__uint_as_float(f2tf(O[j][2]*i1)),
                                                __uint_as_float(f2tf(O[j][3]*i1)));
    }
}

// ---------------------------------------------------------------------------
// Kernel: out = Ctx @ Wo^T + bo
// ---------------------------------------------------------------------------
__global__ void __launch_bounds__(256, 2) out_kernel(
    const float* __restrict__ bo, float* __restrict__ out)
{
    extern __shared__ unsigned smq[];
    unsigned* As = smq;
    unsigned* Bs = smq + 3*128*36;
    const int mBase = blockIdx.x * 128, nBase = blockIdx.y * 128;
    float C[2][8][4] = {};
    gemm_body(g_Ctx, g_Wo, mBase, nBase, As, Bs, C);

    const int t = threadIdx.x, lane = t & 31, warp = t >> 5;
    const int g = lane >> 2, tg = lane & 3;
    const int wm = warp >> 1, wn = warp & 1;
    #pragma unroll
    for (int mi = 0; mi < 2; mi++) {
        #pragma unroll
        for (int j = 0; j < 8; j++) {
            int n = nBase + wn*64 + j*8 + 2*tg;
            float2 bias = *(const float2*)(bo + n);
            #pragma unroll
            for (int hh = 0; hh < 2; hh++) {
                int m = mBase + wm*32 + mi*16 + g + 8*hh;
                float2 v = make_float2(C[mi][j][hh*2] + bias.x, C[mi][j][hh*2+1] + bias.y);
                *(float2*)(out + (size_t)m*D_ + n) = v;
            }
        }
    }
}

// ---------------------------------------------------------------------------
extern "C" void kernel_launch(void* const* d_in, const int* in_sizes, int n_in,
                              void* d_out, int out_size)
{
    const float* x  = (const float*)d_in[0];
    const float* Wq = (const float*)d_in[1];
    const float* Wk = (const float*)d_in[2];
    const float* Wv = (const float*)d_in[3];
    const float* We = (const float*)d_in[4];
    const float* Wo = (const float*)d_in[5];
    const float* bo = (const float*)d_in[6];
    float* out = (float*)d_out;

    const int gemm_smem = 2 * 3 * 128 * 36 * (int)sizeof(unsigned);   // 110592
    const int rel_smem  = 2 * 128 * 68 * (int)sizeof(unsigned);       // 69632
    const int attn_smem = 2*64*68*4 + 64*72*2;                        // 44032
    cudaFuncSetAttribute(qkv_kernel,  cudaFuncAttributeMaxDynamicSharedMemorySize, gemm_smem);
    cudaFuncSetAttribute(rel_kernel,  cudaFuncAttributeMaxDynamicSharedMemorySize, rel_smem);
    cudaFuncSetAttribute(attn_kernel, cudaFuncAttributeMaxDynamicSharedMemorySize, attn_smem);
    cudaFuncSetAttribute(out_kernel,  cudaFuncAttributeMaxDynamicSharedMemorySize, gemm_smem);

    const int prep_total = XN_ + 4*WN_ + L_*DH_;
    prep_kernel<<<(prep_total/4 + 255)/256, 256>>>(x, Wq, Wk, Wv, Wo, We);

    qkv_kernel<<<dim3(M_/128, D_/128, 3), 256, gemm_smem>>>();
    rel_kernel<<<dim3(L_/128, L_/128, BH_), 256, rel_smem>>>();
    attn_kernel<<<dim3(L_/64, BH_), 128, attn_smem>>>();
    out_kernel<<<dim3(M_/128, D_/128), 256, gemm_smem>>>(bo, out);
}

// round 10
// speedup vs baseline: 1.7373x; 1.1474x over previous
#include <cuda_runtime.h>
#include <cuda_bf16.h>
#include <cuda_fp16.h>
#include <math.h>

#define B_  8
#define L_  1024
#define D_  512
#define H_  8
#define DH_ 64
#define M_  (B_*L_)     // 8192
#define BH_ (B_*H_)     // 64

// Scratch (device globals: allocation-free kernel_launch per harness rules)
__device__ __align__(16) __half g_Qh[BH_*L_*DH_];  // fp16, 0.125*log2e-scaled
__device__ __align__(16) __half g_Kh[BH_*L_*DH_];
__device__ __align__(16) __half g_Vh[BH_*L_*DH_];
__device__ __align__(16) float  g_Ctx[M_*D_];      // tf32-rounded, (b,l,D)
__device__ __align__(16) float  g_x [M_*D_];       // tf32-rounded input
__device__ __align__(16) float  g_Wq[D_*D_];
__device__ __align__(16) float  g_Wk[D_*D_];
__device__ __align__(16) float  g_Wv[D_*D_];
__device__ __align__(16) float  g_Wo[D_*D_];
__device__ __align__(16) __half g_Weh[L_*DH_];
__device__ __align__(16) __nv_bfloat16 g_R[(size_t)BH_*L_*L_ + 128]; // bias (log2), padded

// ---------------------------------------------------------------------------
// helpers
// ---------------------------------------------------------------------------
__device__ __forceinline__ unsigned f2tf(float f) {
    unsigned u; asm("cvt.rna.tf32.f32 %0, %1;" : "=r"(u) : "f"(f)); return u;
}
__device__ __forceinline__ void mma8(float* c,
    unsigned a0, unsigned a1, unsigned a2, unsigned a3,
    unsigned b0, unsigned b1)
{
    asm volatile(
        "mma.sync.aligned.m16n8k8.row.col.f32.tf32.tf32.f32 "
        "{%0,%1,%2,%3},{%4,%5,%6,%7},{%8,%9},{%0,%1,%2,%3};"
        : "+f"(c[0]), "+f"(c[1]), "+f"(c[2]), "+f"(c[3])
        : "r"(a0), "r"(a1), "r"(a2), "r"(a3), "r"(b0), "r"(b1));
}
__device__ __forceinline__ void mma16h(float* c,
    unsigned a0, unsigned a1, unsigned a2, unsigned a3,
    unsigned b0, unsigned b1)
{
    asm volatile(
        "mma.sync.aligned.m16n8k16.row.col.f32.f16.f16.f32 "
        "{%0,%1,%2,%3},{%4,%5,%6,%7},{%8,%9},{%0,%1,%2,%3};"
        : "+f"(c[0]), "+f"(c[1]), "+f"(c[2]), "+f"(c[3])
        : "r"(a0), "r"(a1), "r"(a2), "r"(a3), "r"(b0), "r"(b1));
}
__device__ __forceinline__ void ldsm4(unsigned& r0, unsigned& r1,
                                      unsigned& r2, unsigned& r3, unsigned addr)
{
    asm volatile("ldmatrix.sync.aligned.m8n8.x4.shared.b16 {%0,%1,%2,%3}, [%4];"
        : "=r"(r0), "=r"(r1), "=r"(r2), "=r"(r3) : "r"(addr));
}
__device__ __forceinline__ void ldsm4t(unsigned& r0, unsigned& r1,
                                       unsigned& r2, unsigned& r3, unsigned addr)
{
    asm volatile("ldmatrix.sync.aligned.m8n8.x4.trans.shared.b16 {%0,%1,%2,%3}, [%4];"
        : "=r"(r0), "=r"(r1), "=r"(r2), "=r"(r3) : "r"(addr));
}
__device__ __forceinline__ unsigned ex2h2(float lo, float hi) {
    unsigned p;
    asm("cvt.rn.f16x2.f32 %0, %1, %2;" : "=r"(p) : "f"(hi), "f"(lo));
    asm("ex2.approx.f16x2 %0, %0;" : "+r"(p));
    return p;
}
__device__ __forceinline__ unsigned scvta(const void* p) {
    return (unsigned)__cvta_generic_to_shared(p);
}
__device__ __forceinline__ void cpa16(unsigned dst, const void* src) {
    asm volatile("cp.async.cg.shared.global [%0], [%1], 16;" :: "r"(dst), "l"(src));
}
__device__ __forceinline__ void cpa_commit() {
    asm volatile("cp.async.commit_group;");
}
template<int N> __device__ __forceinline__ void cpa_wait() {
    asm volatile("cp.async.wait_group %0;" :: "n"(N));
}

// ---------------------------------------------------------------------------
// Prep: ONE launch. x/W* -> tf32; We -> fp16.
// ---------------------------------------------------------------------------
#define XN_ (M_*D_)
#define WN_ (D_*D_)
__global__ void __launch_bounds__(256) prep_kernel(
    const float* __restrict__ x,  const float* __restrict__ Wq,
    const float* __restrict__ Wk, const float* __restrict__ Wv,
    const float* __restrict__ Wo, const float* __restrict__ We)
{
    int i = (blockIdx.x * 256 + threadIdx.x) * 4;
    if (i >= XN_ + 4*WN_ + L_*DH_) return;
    if (i >= XN_ + 4*WN_) {
        int k = i - XN_ - 4*WN_;
        float4 v = *(const float4*)(We + k);
        *(__half2*)(g_Weh + k)     = __floats2half2_rn(v.x, v.y);
        *(__half2*)(g_Weh + k + 2) = __floats2half2_rn(v.z, v.w);
        return;
    }
    const float* s; float* d;
    if      (i < XN_)          { s = x  + i;               d = g_x  + i; }
    else if (i < XN_ + WN_)    { s = Wq + i - XN_;         d = g_Wq + i - XN_; }
    else if (i < XN_ + 2*WN_)  { s = Wk + i - XN_ - WN_;   d = g_Wk + i - XN_ - WN_; }
    else if (i < XN_ + 3*WN_)  { s = Wv + i - XN_ - 2*WN_; d = g_Wv + i - XN_ - 2*WN_; }
    else                       { s = Wo + i - XN_ - 3*WN_; d = g_Wo + i - XN_ - 3*WN_; }
    float4 v = *(const float4*)s;
    *(uint4*)d = make_uint4(f2tf(v.x), f2tf(v.y), f2tf(v.z), f2tf(v.w));
}

// ---------------------------------------------------------------------------
// Dense GEMM body (K=512, tf32): C(128x128) = A * W^T. 3-stage cp.async.
// ---------------------------------------------------------------------------
__device__ __forceinline__ void gemm_body(
    const float* __restrict__ A, const float* __restrict__ W,
    int mBase, int nBase, unsigned* As, unsigned* Bs, float C[2][8][4])
{
    const int t = threadIdx.x, lane = t & 31, warp = t >> 5;
    const int wm = warp >> 1, wn = warp & 1;
    const int lr = t >> 3, lc = (t & 7) * 4;
    const int BUF = 128 * 36;

    unsigned as_a = scvta(As + lr*36 + lc);
    unsigned bs_a = scvta(Bs + lr*36 + lc);

    auto stage = [&](int buf, int k0) {
        #pragma unroll
        for (int i = 0; i < 4; i++) {
            unsigned off = (unsigned)(buf*BUF + i*32*36) * 4u;
            cpa16(as_a + off, A + (size_t)(mBase + lr + 32*i) * D_ + k0 + lc);
            cpa16(bs_a + off, W + (size_t)(nBase + lr + 32*i) * D_ + k0 + lc);
        }
        cpa_commit();
    };

    const int lr8 = lane & 7;
    unsigned aAddr = scvta(As) +
        (unsigned)(((wm*32 + lr8 + ((lane & 8) ? 8 : 0))*36 + ((lane & 16) ? 4 : 0)) * 4);
    unsigned bAddr = scvta(Bs) +
        (unsigned)(((wn*64 + lr8 + ((lane & 16) ? 8 : 0))*36 + ((lane & 8) ? 4 : 0)) * 4);

    stage(0, 0);
    stage(1, 32);
    int cb = 0, nb = 2, nk = 64;
    for (int it = 0; it < 16; it++) {
        cpa_wait<1>();
        __syncthreads();
        if (it + 2 < 16) {
            stage(nb, nk);
            nk += 32;
            nb = (nb == 2) ? 0 : nb + 1;
        }
        const unsigned bo = (unsigned)(cb * BUF * 4);
        #pragma unroll
        for (int kk = 0; kk < 32; kk += 8) {
            unsigned a[2][4];
            #pragma unroll
            for (int mi = 0; mi < 2; mi++)
                ldsm4(a[mi][0], a[mi][1], a[mi][2], a[mi][3],
                      aAddr + bo + (unsigned)((mi*16*36 + kk) * 4));
            #pragma unroll
            for (int jp = 0; jp < 4; jp++) {
                unsigned b0, b1, b2, b3;
                ldsm4(b0, b1, b2, b3, bAddr + bo + (unsigned)((jp*16*36 + kk) * 4));
                mma8(C[0][jp*2],   a[0][0], a[0][1], a[0][2], a[0][3], b0, b1);
                mma8(C[0][jp*2+1], a[0][0], a[0][1], a[0][2], a[0][3], b2, b3);
                mma8(C[1][jp*2],   a[1][0], a[1][1], a[1][2], a[1][3], b0, b1);
                mma8(C[1][jp*2+1], a[1][0], a[1][1], a[1][2], a[1][3], b2, b3);
            }
        }
        cb = (cb == 2) ? 0 : cb + 1;
    }
}

// ---------------------------------------------------------------------------
// Kernel: QKV projections -> fp16 (b,h,l,dh). Q scaled by 0.125*log2(e).
// ---------------------------------------------------------------------------
__global__ void __launch_bounds__(256, 2) qkv_kernel()
{
    extern __shared__ unsigned smq[];
    unsigned* As = smq;
    unsigned* Bs = smq + 3*128*36;
    const float* W = (blockIdx.z == 0) ? g_Wq : (blockIdx.z == 1) ? g_Wk : g_Wv;
    __half* dst    = (blockIdx.z == 0) ? g_Qh : (blockIdx.z == 1) ? g_Kh : g_Vh;
    const float scale = (blockIdx.z == 0) ? 0.125f * 1.4426950408889634f : 1.0f;
    const int mBase = blockIdx.x * 128, nBase = blockIdx.y * 128;
    float C[2][8][4] = {};
    gemm_body(g_x, W, mBase, nBase, As, Bs, C);

    const int t = threadIdx.x, lane = t & 31, warp = t >> 5;
    const int g = lane >> 2, tg = lane & 3;
    const int wm = warp >> 1, wn = warp & 1;
    #pragma unroll
    for (int mi = 0; mi < 2; mi++) {
        #pragma unroll
        for (int j = 0; j < 8; j++) {
            int n = nBase + wn*64 + j*8 + 2*tg;
            int h = n >> 6, dh = n & 63;
            #pragma unroll
            for (int hh = 0; hh < 2; hh++) {
                int m = mBase + wm*32 + mi*16 + g + 8*hh;
                int b = m >> 10, l = m & (L_-1);
                __half2 v = __floats2half2_rn(C[mi][j][hh*2]*scale, C[mi][j][hh*2+1]*scale);
                *(__half2*)(dst + ((size_t)((b*H_+h)*L_ + l))*DH_ + dh) = v;
            }
        }
    }
}

// ---------------------------------------------------------------------------
// Kernel: R[bh][l][e] = Qh[bh,l,:].Weh[e,:] (fp16 mma, K=64), bf16 output
// ---------------------------------------------------------------------------
__global__ void __launch_bounds__(256, 2) rel_kernel()
{
    extern __shared__ __half smr[];
    __half* Ah = smr;               // 128 x 72 halves
    __half* Bh = smr + 128*72;
    const int bh = blockIdx.z;
    const int mBase = blockIdx.x * 128, nBase = blockIdx.y * 128;
    const __half* A  = g_Qh + (size_t)bh * L_ * DH_;
    const __half* Wb = g_Weh;

    const int t = threadIdx.x, lane = t & 31, warp = t >> 5;
    const int wm = warp >> 1, wn = warp & 1;

    const int lr2 = t >> 1, lc2 = (t & 1) * 4;
    unsigned a_a = scvta(Ah) + (unsigned)(lr2*144);
    unsigned b_a = scvta(Bh) + (unsigned)(lr2*144);
    #pragma unroll
    for (int i = 0; i < 4; i++) {
        int ci = lc2 + i;
        cpa16(a_a + ci*16, A  + (size_t)(mBase + lr2) * DH_ + ci*8);
        cpa16(b_a + ci*16, Wb + (size_t)(nBase + lr2) * DH_ + ci*8);
    }
    cpa_commit(); cpa_wait<0>();
    __syncthreads();

    const int lr8 = lane & 7;
    unsigned aAddr = scvta(Ah) +
        (unsigned)(((wm*32 + (lane & 15))*72 + ((lane >> 4)*8)) * 2);
    unsigned bAddr = scvta(Bh) +
        (unsigned)(((wn*64 + lr8 + ((lane & 16) ? 8 : 0))*72 + ((lane & 8) ? 8 : 0)) * 2);

    float C[2][8][4] = {};
    #pragma unroll
    for (int k0 = 0; k0 < 64; k0 += 16) {
        unsigned a[2][4];
        #pragma unroll
        for (int mi = 0; mi < 2; mi++)
            ldsm4(a[mi][0], a[mi][1], a[mi][2], a[mi][3],
                  aAddr + (unsigned)((mi*16*72 + k0) * 2));
        #pragma unroll
        for (int jp = 0; jp < 4; jp++) {
            unsigned b0, b1, b2, b3;
            ldsm4(b0, b1, b2, b3, bAddr + (unsigned)((jp*16*72 + k0) * 2));
            mma16h(C[0][jp*2],   a[0][0], a[0][1], a[0][2], a[0][3], b0, b1);
            mma16h(C[0][jp*2+1], a[0][0], a[0][1], a[0][2], a[0][3], b2, b3);
            mma16h(C[1][jp*2],   a[1][0], a[1][1], a[1][2], a[1][3], b0, b1);
            mma16h(C[1][jp*2+1], a[1][0], a[1][1], a[1][2], a[1][3], b2, b3);
        }
    }

    const int g = lane >> 2, tg = lane & 3;
    __nv_bfloat16* Rb = g_R + (size_t)bh * L_ * L_;
    #pragma unroll
    for (int mi = 0; mi < 2; mi++) {
        #pragma unroll
        for (int j = 0; j < 8; j++) {
            int n = nBase + wn*64 + j*8 + 2*tg;
            #pragma unroll
            for (int hh = 0; hh < 2; hh++) {
                int m = mBase + wm*32 + mi*16 + g + 8*hh;
                __nv_bfloat162 v = make_bfloat162(
                    __float2bfloat16_rn(C[mi][j][hh*2]),
                    __float2bfloat16_rn(C[mi][j][hh*2+1]));
                *(__nv_bfloat162*)(Rb + (size_t)m*L_ + n) = v;
            }
        }
    }
}

// ---------------------------------------------------------------------------
// Kernel: flash attention, all-fp16 MMA path. Bias via per-row 80-wide
// aligned R-windows staged with cp.async, gathered from smem.
// ---------------------------------------------------------------------------
__global__ void __launch_bounds__(128, 4) attn_kernel()
{
    extern __shared__ __half sma[];
    __half* Qh = sma;               // 64 x 72 halves [l][dh]
    __half* Kh = Qh + 64*72;        // [s][dh]
    __half* Vh = Kh + 64*72;        // [s][dh]
    __half* Rw = Vh + 64*72;        // 64 x 80 halves (bf16 bits) bias windows

    const int bh = blockIdx.y, lBase = blockIdx.x * 64;
    const __half* __restrict__ Qg = g_Qh + (size_t)bh * L_ * DH_;
    const __half* __restrict__ Kg = g_Kh + (size_t)bh * L_ * DH_;
    const __half* __restrict__ Vg = g_Vh + (size_t)bh * L_ * DH_;
    const __nv_bfloat16* __restrict__ Rg = g_R + ((size_t)bh << 20);

    const int t = threadIdx.x, lane = t & 31, warp = t >> 5;
    const int g = lane >> 2, tg = lane & 3;
    const int rA = warp*16 + g;

    const int srow = t & 63, scb = (t >> 6) * 4;
    unsigned q_a = scvta(Qh) + (unsigned)(srow*144);
    unsigned k_a = scvta(Kh) + (unsigned)(srow*144);
    unsigned v_a = scvta(Vh) + (unsigned)(srow*144);
    const int rrow = t >> 1, rcb = (t & 1) * 5;
    unsigned r_a = scvta(Rw) + (unsigned)(rrow*160);
    const int rl = lBase + rrow;
    const __nv_bfloat16* Rrow = Rg + ((size_t)rl << 10);

    auto admax = [](int l, int sB) {
        int a0 = l - sB;      if (a0 < 0) a0 = -a0;
        int a1 = l - sB - 63; if (a1 < 0) a1 = -a1;
        return a0 > a1 ? a0 : a1;
    };

    {   // stage Q + first K/V/bias tiles
        #pragma unroll
        for (int i = 0; i < 4; i++) {
            int ci = scb + i;
            cpa16(q_a + ci*16, Qg + (size_t)(lBase + srow)*DH_ + ci*8);
            cpa16(k_a + ci*16, Kg + (size_t)srow*DH_ + ci*8);
            cpa16(v_a + ci*16, Vg + (size_t)srow*DH_ + ci*8);
        }
        int e_lo8 = (1023 - admax(rl, 0)) & ~7;
        #pragma unroll
        for (int i = 0; i < 5; i++) {
            int ci = rcb + i;
            cpa16(r_a + ci*16, Rrow + e_lo8 + ci*8);
        }
        cpa_commit();
    }

    const int lr8 = lane & 7;
    unsigned aQ = scvta(Qh) +
        (unsigned)(((warp*16 + (lane & 15))*72 + ((lane >> 4)*8)) * 2);
    unsigned bK0 = scvta(Kh) +
        (unsigned)(((lr8 + ((lane & 16) ? 8 : 0))*72 + ((lane & 8) ? 8 : 0)) * 2);
    unsigned bV0 = scvta(Vh) +
        (unsigned)(((lane & 15)*72 + (lane >> 4)*8) * 2);

    const unsigned ONES = 0x3C003C00u;
    float lsum[4] = {0.f, 0.f, 0.f, 0.f};
    float O[8][4] = {};

    const int lg0 = lBase + rA, lg1 = lg0 + 8;

    for (int sBase = 0; sBase < L_; sBase += 64) {
        const int base0 = 1023 - ((1023 - admax(lg0, sBase)) & ~7);
        const int base1 = 1023 - ((1023 - admax(lg1, sBase)) & ~7);

        cpa_wait<0>();
        __syncthreads();                                    // (1) tiles visible

        // ---- sf init: gather bias from staged windows (LDS) ----
        float sf[8][4];
        #pragma unroll
        for (int j = 0; j < 8; j++) {
            int c0 = sBase + j*8 + 2*tg;
            #pragma unroll
            for (int q = 0; q < 4; q++) {
                int col  = c0 + (q & 1);
                int lg   = (q < 2) ? lg0 : lg1;
                int rloc = (q < 2) ? rA  : rA + 8;
                int base = (q < 2) ? base0 : base1;
                int d = lg - col; int ad = d < 0 ? -d : d;
                unsigned short hv = *(const unsigned short*)&Rw[rloc*80 + (base - ad)];
                sf[j][q] = __bfloat162float(*(const __nv_bfloat16*)&hv);
            }
        }

        // ---- S GEMM (fp16, accumulates onto bias) ----
        #pragma unroll
        for (int k0 = 0; k0 < 64; k0 += 16) {
            unsigned a0, a1, a2, a3;
            ldsm4(a0, a1, a2, a3, aQ + (unsigned)(k0*2));
            #pragma unroll
            for (int jp = 0; jp < 4; jp++) {
                unsigned b0, b1, b2, b3;
                ldsm4(b0, b1, b2, b3, bK0 + (unsigned)((jp*16*72 + k0) * 2));
                mma16h(sf[jp*2],   a0, a1, a2, a3, b0, b1);
                mma16h(sf[jp*2+1], a0, a1, a2, a3, b2, b3);
            }
        }

        // ---- fp16 softmax tail + PV ----
        #pragma unroll
        for (int j2 = 0; j2 < 4; j2++) {
            const int jb0 = 2*j2, jb1 = 2*j2 + 1;
            unsigned a0 = ex2h2(sf[jb0][0], sf[jb0][1]);
            unsigned a1 = ex2h2(sf[jb0][2], sf[jb0][3]);
            unsigned a2 = ex2h2(sf[jb1][0], sf[jb1][1]);
            unsigned a3 = ex2h2(sf[jb1][2], sf[jb1][3]);
            mma16h(lsum, a0, a1, a2, a3, ONES, ONES);
            #pragma unroll
            for (int jp = 0; jp < 4; jp++) {
                unsigned b0, b1, b2, b3;
                ldsm4t(b0, b1, b2, b3, bV0 + (unsigned)((j2*16*72 + jp*16) * 2));
                mma16h(O[jp*2],   a0, a1, a2, a3, b0, b1);
                mma16h(O[jp*2+1], a0, a1, a2, a3, b2, b3);
            }
        }
        __syncthreads();                                    // (2) tiles reusable

        if (sBase + 64 < L_) {
            int sn = sBase + 64;
            #pragma unroll
            for (int i = 0; i < 4; i++) {
                int ci = scb + i;
                cpa16(k_a + ci*16, Kg + (size_t)(sn + srow)*DH_ + ci*8);
                cpa16(v_a + ci*16, Vg + (size_t)(sn + srow)*DH_ + ci*8);
            }
            int e_lo8 = (1023 - admax(rl, sn)) & ~7;
            #pragma unroll
            for (int i = 0; i < 5; i++) {
                int ci = rcb + i;
                cpa16(r_a + ci*16, Rrow + e_lo8 + ci*8);
            }
            cpa_commit();
        }
    }

    // normalize + write ctx
    const float i0 = 1.0f / lsum[0], i1 = 1.0f / lsum[2];
    const int b = bh >> 3, hh = bh & 7;
    #pragma unroll
    for (int j = 0; j < 8; j++) {
        int dh = j*8 + 2*tg;
        size_t base0 = ((size_t)(b*L_ + lBase + rA))*D_ + hh*DH_ + dh;
        size_t base1 = ((size_t)(b*L_ + lBase + rA + 8))*D_ + hh*DH_ + dh;
        *(float2*)(g_Ctx + base0) = make_float2(__uint_as_float(f2tf(O[j][0]*i0)),
                                                __uint_as_float(f2tf(O[j][1]*i0)));
        *(float2*)(g_Ctx + base1) = make_float2(__uint_as_float(f2tf(O[j][2]*i1)),
                                                __uint_as_float(f2tf(O[j][3]*i1)));
    }
}

// ---------------------------------------------------------------------------
// Kernel: out = Ctx @ Wo^T + bo
// ---------------------------------------------------------------------------
__global__ void __launch_bounds__(256, 2) out_kernel(
    const float* __restrict__ bo, float* __restrict__ out)
{
    extern __shared__ unsigned smq[];
    unsigned* As = smq;
    unsigned* Bs = smq + 3*128*36;
    const int mBase = blockIdx.x * 128, nBase = blockIdx.y * 128;
    float C[2][8][4] = {};
    gemm_body(g_Ctx, g_Wo, mBase, nBase, As, Bs, C);

    const int t = threadIdx.x, lane = t & 31, warp = t >> 5;
    const int g = lane >> 2, tg = lane & 3;
    const int wm = warp >> 1, wn = warp & 1;
    #pragma unroll
    for (int mi = 0; mi < 2; mi++) {
        #pragma unroll
        for (int j = 0; j < 8; j++) {
            int n = nBase + wn*64 + j*8 + 2*tg;
            float2 bias = *(const float2*)(bo + n);
            #pragma unroll
            for (int hh = 0; hh < 2; hh++) {
                int m = mBase + wm*32 + mi*16 + g + 8*hh;
                float2 v = make_float2(C[mi][j][hh*2] + bias.x, C[mi][j][hh*2+1] + bias.y);
                *(float2*)(out + (size_t)m*D_ + n) = v;
            }
        }
    }
}

// ---------------------------------------------------------------------------
extern "C" void kernel_launch(void* const* d_in, const int* in_sizes, int n_in,
                              void* d_out, int out_size)
{
    const float* x  = (const float*)d_in[0];
    const float* Wq = (const float*)d_in[1];
    const float* Wk = (const float*)d_in[2];
    const float* Wv = (const float*)d_in[3];
    const float* We = (const float*)d_in[4];
    const float* Wo = (const float*)d_in[5];
    const float* bo = (const float*)d_in[6];
    float* out = (float*)d_out;

    const int gemm_smem = 2 * 3 * 128 * 36 * (int)sizeof(unsigned);      // 110592
    const int rel_smem  = 2 * 128 * 72 * (int)sizeof(__half);            // 36864
    const int attn_smem = (3 * 64 * 72 + 64 * 80) * (int)sizeof(__half); // 37888
    cudaFuncSetAttribute(qkv_kernel,  cudaFuncAttributeMaxDynamicSharedMemorySize, gemm_smem);
    cudaFuncSetAttribute(rel_kernel,  cudaFuncAttributeMaxDynamicSharedMemorySize, rel_smem);
    cudaFuncSetAttribute(attn_kernel, cudaFuncAttributeMaxDynamicSharedMemorySize, attn_smem);
    cudaFuncSetAttribute(out_kernel,  cudaFuncAttributeMaxDynamicSharedMemorySize, gemm_smem);

    const int prep_total = XN_ + 4*WN_ + L_*DH_;
    prep_kernel<<<(prep_total/4 + 255)/256, 256>>>(x, Wq, Wk, Wv, Wo, We);

    qkv_kernel<<<dim3(M_/128, D_/128, 3), 256, gemm_smem>>>();
    rel_kernel<<<dim3(L_/128, L_/128, BH_), 256, rel_smem>>>();
    attn_kernel<<<dim3(L_/64, BH_), 128, attn_smem>>>();
    out_kernel<<<dim3(M_/128, D_/128), 256, gemm_smem>>>(bo, out);
}

// round 11
// speedup vs baseline: 1.7787x; 1.0238x over previous
#include <cuda_runtime.h>
#include <cuda_bf16.h>
#include <cuda_fp16.h>
#include <math.h>

#define B_  8
#define L_  1024
#define D_  512
#define H_  8
#define DH_ 64
#define M_  (B_*L_)     // 8192
#define BH_ (B_*H_)     // 64

// Scratch (device globals: allocation-free kernel_launch per harness rules)
__device__ __align__(16) __half g_Qh[BH_*L_*DH_];  // fp16, 0.125*log2e-scaled
__device__ __align__(16) __half g_Kh[BH_*L_*DH_];
__device__ __align__(16) __half g_Vh[BH_*L_*DH_];
__device__ __align__(16) float  g_Ctx[M_*D_];      // tf32-rounded, (b,l,D)
__device__ __align__(16) float  g_x [M_*D_];       // tf32-rounded input
__device__ __align__(16) float  g_Wq[D_*D_];
__device__ __align__(16) float  g_Wk[D_*D_];
__device__ __align__(16) float  g_Wv[D_*D_];
__device__ __align__(16) float  g_Wo[D_*D_];
__device__ __align__(16) __half g_Weh[L_*DH_];
__device__ __align__(16) __nv_bfloat16 g_R[(size_t)BH_*L_*L_ + 128]; // bias (log2), padded

// ---------------------------------------------------------------------------
// helpers
// ---------------------------------------------------------------------------
__device__ __forceinline__ unsigned f2tf(float f) {
    unsigned u; asm("cvt.rna.tf32.f32 %0, %1;" : "=r"(u) : "f"(f)); return u;
}
__device__ __forceinline__ void mma8(float* c,
    unsigned a0, unsigned a1, unsigned a2, unsigned a3,
    unsigned b0, unsigned b1)
{
    asm volatile(
        "mma.sync.aligned.m16n8k8.row.col.f32.tf32.tf32.f32 "
        "{%0,%1,%2,%3},{%4,%5,%6,%7},{%8,%9},{%0,%1,%2,%3};"
        : "+f"(c[0]), "+f"(c[1]), "+f"(c[2]), "+f"(c[3])
        : "r"(a0), "r"(a1), "r"(a2), "r"(a3), "r"(b0), "r"(b1));
}
__device__ __forceinline__ void mma16h(float* c,
    unsigned a0, unsigned a1, unsigned a2, unsigned a3,
    unsigned b0, unsigned b1)
{
    asm volatile(
        "mma.sync.aligned.m16n8k16.row.col.f32.f16.f16.f32 "
        "{%0,%1,%2,%3},{%4,%5,%6,%7},{%8,%9},{%0,%1,%2,%3};"
        : "+f"(c[0]), "+f"(c[1]), "+f"(c[2]), "+f"(c[3])
        : "r"(a0), "r"(a1), "r"(a2), "r"(a3), "r"(b0), "r"(b1));
}
__device__ __forceinline__ void ldsm4(unsigned& r0, unsigned& r1,
                                      unsigned& r2, unsigned& r3, unsigned addr)
{
    asm volatile("ldmatrix.sync.aligned.m8n8.x4.shared.b16 {%0,%1,%2,%3}, [%4];"
        : "=r"(r0), "=r"(r1), "=r"(r2), "=r"(r3) : "r"(addr));
}
__device__ __forceinline__ void ldsm4t(unsigned& r0, unsigned& r1,
                                       unsigned& r2, unsigned& r3, unsigned addr)
{
    asm volatile("ldmatrix.sync.aligned.m8n8.x4.trans.shared.b16 {%0,%1,%2,%3}, [%4];"
        : "=r"(r0), "=r"(r1), "=r"(r2), "=r"(r3) : "r"(addr));
}
__device__ __forceinline__ unsigned ex2h2(float lo, float hi) {
    unsigned p;
    asm("cvt.rn.f16x2.f32 %0, %1, %2;" : "=r"(p) : "f"(hi), "f"(lo));
    asm("ex2.approx.f16x2 %0, %0;" : "+r"(p));
    return p;
}
__device__ __forceinline__ unsigned scvta(const void* p) {
    return (unsigned)__cvta_generic_to_shared(p);
}
__device__ __forceinline__ void cpa16(unsigned dst, const void* src) {
    asm volatile("cp.async.cg.shared.global [%0], [%1], 16;" :: "r"(dst), "l"(src));
}
__device__ __forceinline__ void cpa_commit() {
    asm volatile("cp.async.commit_group;");
}
template<int N> __device__ __forceinline__ void cpa_wait() {
    asm volatile("cp.async.wait_group %0;" :: "n"(N));
}

// ---------------------------------------------------------------------------
// Prep: ONE launch. x/W* -> tf32; We -> fp16.
// ---------------------------------------------------------------------------
#define XN_ (M_*D_)
#define WN_ (D_*D_)
__global__ void __launch_bounds__(256) prep_kernel(
    const float* __restrict__ x,  const float* __restrict__ Wq,
    const float* __restrict__ Wk, const float* __restrict__ Wv,
    const float* __restrict__ Wo, const float* __restrict__ We)
{
    int i = (blockIdx.x * 256 + threadIdx.x) * 4;
    if (i >= XN_ + 4*WN_ + L_*DH_) return;
    if (i >= XN_ + 4*WN_) {
        int k = i - XN_ - 4*WN_;
        float4 v = *(const float4*)(We + k);
        *(__half2*)(g_Weh + k)     = __floats2half2_rn(v.x, v.y);
        *(__half2*)(g_Weh + k + 2) = __floats2half2_rn(v.z, v.w);
        return;
    }
    const float* s; float* d;
    if      (i < XN_)          { s = x  + i;               d = g_x  + i; }
    else if (i < XN_ + WN_)    { s = Wq + i - XN_;         d = g_Wq + i - XN_; }
    else if (i < XN_ + 2*WN_)  { s = Wk + i - XN_ - WN_;   d = g_Wk + i - XN_ - WN_; }
    else if (i < XN_ + 3*WN_)  { s = Wv + i - XN_ - 2*WN_; d = g_Wv + i - XN_ - 2*WN_; }
    else                       { s = Wo + i - XN_ - 3*WN_; d = g_Wo + i - XN_ - 3*WN_; }
    float4 v = *(const float4*)s;
    *(uint4*)d = make_uint4(f2tf(v.x), f2tf(v.y), f2tf(v.z), f2tf(v.w));
}

// ---------------------------------------------------------------------------
// Dense GEMM body (K=512, tf32): C(128x128) = A * W^T. 3-stage cp.async.
// ---------------------------------------------------------------------------
__device__ __forceinline__ void gemm_body(
    const float* __restrict__ A, const float* __restrict__ W,
    int mBase, int nBase, unsigned* As, unsigned* Bs, float C[2][8][4])
{
    const int t = threadIdx.x, lane = t & 31, warp = t >> 5;
    const int wm = warp >> 1, wn = warp & 1;
    const int lr = t >> 3, lc = (t & 7) * 4;
    const int BUF = 128 * 36;

    unsigned as_a = scvta(As + lr*36 + lc);
    unsigned bs_a = scvta(Bs + lr*36 + lc);

    auto stage = [&](int buf, int k0) {
        #pragma unroll
        for (int i = 0; i < 4; i++) {
            unsigned off = (unsigned)(buf*BUF + i*32*36) * 4u;
            cpa16(as_a + off, A + (size_t)(mBase + lr + 32*i) * D_ + k0 + lc);
            cpa16(bs_a + off, W + (size_t)(nBase + lr + 32*i) * D_ + k0 + lc);
        }
        cpa_commit();
    };

    const int lr8 = lane & 7;
    unsigned aAddr = scvta(As) +
        (unsigned)(((wm*32 + lr8 + ((lane & 8) ? 8 : 0))*36 + ((lane & 16) ? 4 : 0)) * 4);
    unsigned bAddr = scvta(Bs) +
        (unsigned)(((wn*64 + lr8 + ((lane & 16) ? 8 : 0))*36 + ((lane & 8) ? 4 : 0)) * 4);

    stage(0, 0);
    stage(1, 32);
    int cb = 0, nb = 2, nk = 64;
    for (int it = 0; it < 16; it++) {
        cpa_wait<1>();
        __syncthreads();
        if (it + 2 < 16) {
            stage(nb, nk);
            nk += 32;
            nb = (nb == 2) ? 0 : nb + 1;
        }
        const unsigned bo = (unsigned)(cb * BUF * 4);
        #pragma unroll
        for (int kk = 0; kk < 32; kk += 8) {
            unsigned a[2][4];
            #pragma unroll
            for (int mi = 0; mi < 2; mi++)
                ldsm4(a[mi][0], a[mi][1], a[mi][2], a[mi][3],
                      aAddr + bo + (unsigned)((mi*16*36 + kk) * 4));
            #pragma unroll
            for (int jp = 0; jp < 4; jp++) {
                unsigned b0, b1, b2, b3;
                ldsm4(b0, b1, b2, b3, bAddr + bo + (unsigned)((jp*16*36 + kk) * 4));
                mma8(C[0][jp*2],   a[0][0], a[0][1], a[0][2], a[0][3], b0, b1);
                mma8(C[0][jp*2+1], a[0][0], a[0][1], a[0][2], a[0][3], b2, b3);
                mma8(C[1][jp*2],   a[1][0], a[1][1], a[1][2], a[1][3], b0, b1);
                mma8(C[1][jp*2+1], a[1][0], a[1][1], a[1][2], a[1][3], b2, b3);
            }
        }
        cb = (cb == 2) ? 0 : cb + 1;
    }
}

// ---------------------------------------------------------------------------
// Kernel: QKV projections -> fp16 (b,h,l,dh). Q scaled by 0.125*log2(e).
// ---------------------------------------------------------------------------
__global__ void __launch_bounds__(256, 2) qkv_kernel()
{
    extern __shared__ unsigned smq[];
    unsigned* As = smq;
    unsigned* Bs = smq + 3*128*36;
    const float* W = (blockIdx.z == 0) ? g_Wq : (blockIdx.z == 1) ? g_Wk : g_Wv;
    __half* dst    = (blockIdx.z == 0) ? g_Qh : (blockIdx.z == 1) ? g_Kh : g_Vh;
    const float scale = (blockIdx.z == 0) ? 0.125f * 1.4426950408889634f : 1.0f;
    const int mBase = blockIdx.x * 128, nBase = blockIdx.y * 128;
    float C[2][8][4] = {};
    gemm_body(g_x, W, mBase, nBase, As, Bs, C);

    const int t = threadIdx.x, lane = t & 31, warp = t >> 5;
    const int g = lane >> 2, tg = lane & 3;
    const int wm = warp >> 1, wn = warp & 1;
    #pragma unroll
    for (int mi = 0; mi < 2; mi++) {
        #pragma unroll
        for (int j = 0; j < 8; j++) {
            int n = nBase + wn*64 + j*8 + 2*tg;
            int h = n >> 6, dh = n & 63;
            #pragma unroll
            for (int hh = 0; hh < 2; hh++) {
                int m = mBase + wm*32 + mi*16 + g + 8*hh;
                int b = m >> 10, l = m & (L_-1);
                __half2 v = __floats2half2_rn(C[mi][j][hh*2]*scale, C[mi][j][hh*2+1]*scale);
                *(__half2*)(dst + ((size_t)((b*H_+h)*L_ + l))*DH_ + dh) = v;
            }
        }
    }
}

// ---------------------------------------------------------------------------
// Kernel: R[bh][l][e] = Qh[bh,l,:].Weh[e,:] (fp16 mma, K=64), bf16 output
// ---------------------------------------------------------------------------
__global__ void __launch_bounds__(256, 2) rel_kernel()
{
    extern __shared__ __half smr[];
    __half* Ah = smr;               // 128 x 72 halves
    __half* Bh = smr + 128*72;
    const int bh = blockIdx.z;
    const int mBase = blockIdx.x * 128, nBase = blockIdx.y * 128;
    const __half* A  = g_Qh + (size_t)bh * L_ * DH_;
    const __half* Wb = g_Weh;

    const int t = threadIdx.x, lane = t & 31, warp = t >> 5;
    const int wm = warp >> 1, wn = warp & 1;

    const int lr2 = t >> 1, lc2 = (t & 1) * 4;
    unsigned a_a = scvta(Ah) + (unsigned)(lr2*144);
    unsigned b_a = scvta(Bh) + (unsigned)(lr2*144);
    #pragma unroll
    for (int i = 0; i < 4; i++) {
        int ci = lc2 + i;
        cpa16(a_a + ci*16, A  + (size_t)(mBase + lr2) * DH_ + ci*8);
        cpa16(b_a + ci*16, Wb + (size_t)(nBase + lr2) * DH_ + ci*8);
    }
    cpa_commit(); cpa_wait<0>();
    __syncthreads();

    const int lr8 = lane & 7;
    unsigned aAddr = scvta(Ah) +
        (unsigned)(((wm*32 + (lane & 15))*72 + ((lane >> 4)*8)) * 2);
    unsigned bAddr = scvta(Bh) +
        (unsigned)(((wn*64 + lr8 + ((lane & 16) ? 8 : 0))*72 + ((lane & 8) ? 8 : 0)) * 2);

    float C[2][8][4] = {};
    #pragma unroll
    for (int k0 = 0; k0 < 64; k0 += 16) {
        unsigned a[2][4];
        #pragma unroll
        for (int mi = 0; mi < 2; mi++)
            ldsm4(a[mi][0], a[mi][1], a[mi][2], a[mi][3],
                  aAddr + (unsigned)((mi*16*72 + k0) * 2));
        #pragma unroll
        for (int jp = 0; jp < 4; jp++) {
            unsigned b0, b1, b2, b3;
            ldsm4(b0, b1, b2, b3, bAddr + (unsigned)((jp*16*72 + k0) * 2));
            mma16h(C[0][jp*2],   a[0][0], a[0][1], a[0][2], a[0][3], b0, b1);
            mma16h(C[0][jp*2+1], a[0][0], a[0][1], a[0][2], a[0][3], b2, b3);
            mma16h(C[1][jp*2],   a[1][0], a[1][1], a[1][2], a[1][3], b0, b1);
            mma16h(C[1][jp*2+1], a[1][0], a[1][1], a[1][2], a[1][3], b2, b3);
        }
    }

    const int g = lane >> 2, tg = lane & 3;
    __nv_bfloat16* Rb = g_R + (size_t)bh * L_ * L_;
    #pragma unroll
    for (int mi = 0; mi < 2; mi++) {
        #pragma unroll
        for (int j = 0; j < 8; j++) {
            int n = nBase + wn*64 + j*8 + 2*tg;
            #pragma unroll
            for (int hh = 0; hh < 2; hh++) {
                int m = mBase + wm*32 + mi*16 + g + 8*hh;
                __nv_bfloat162 v = make_bfloat162(
                    __float2bfloat16_rn(C[mi][j][hh*2]),
                    __float2bfloat16_rn(C[mi][j][hh*2+1]));
                *(__nv_bfloat162*)(Rb + (size_t)m*L_ + n) = v;
            }
        }
    }
}

// ---------------------------------------------------------------------------
// Kernel: flash attention v2. 256 threads, 128-row q-tiles (K/V traffic
// halved), DOUBLE-BUFFERED K/V/bias staging so cp.async for tile i+1
// overlaps compute of tile i. fp16 mma everywhere, ex2.f16x2 softmax,
// row sums via ones-mma, zero shuffles.
// ---------------------------------------------------------------------------
__global__ void __launch_bounds__(256, 2) attn_kernel()
{
    extern __shared__ __half sma[];
    __half* Qh = sma;                    // 128 x 72
    __half* Kh = Qh + 128*72;            // 2 buf x 64 x 72
    __half* Vh = Kh + 2*64*72;           // 2 buf x 64 x 72
    __half* Rw = Vh + 2*64*72;           // 2 buf x 128 x 80

    const int KVB = 64*72;               // halves per K/V buffer
    const int RWB = 128*80;              // halves per Rw buffer

    const int bh = blockIdx.y, lBase = blockIdx.x * 128;
    const __half* __restrict__ Qg = g_Qh + (size_t)bh * L_ * DH_;
    const __half* __restrict__ Kg = g_Kh + (size_t)bh * L_ * DH_;
    const __half* __restrict__ Vg = g_Vh + (size_t)bh * L_ * DH_;
    const __nv_bfloat16* __restrict__ Rg = g_R + ((size_t)bh << 20);

    const int t = threadIdx.x, lane = t & 31, warp = t >> 5;
    const int g = lane >> 2, tg = lane & 3;
    const int rA = warp*16 + g;          // 0..127

    // staging maps (256 threads)
    const int qrow = t >> 1, qcb = (t & 1) * 4;   // Q: 2 thr/row, 4 chunks
    const int krow = t & 63, kcb = (t >> 6) * 2;  // K/V: 4 thr/row, 2 chunks
    const int rrow = t >> 1, rcb = (t & 1) * 5;   // Rw: 2 thr/row, 5 chunks
    unsigned q_a = scvta(Qh) + (unsigned)(qrow*144);
    unsigned k_a = scvta(Kh) + (unsigned)(krow*144);
    unsigned v_a = scvta(Vh) + (unsigned)(krow*144);
    unsigned r_a = scvta(Rw) + (unsigned)(rrow*160);
    const int rl = lBase + rrow;
    const __nv_bfloat16* Rrow = Rg + ((size_t)rl << 10);

    auto admax = [](int l, int sB) {
        int a0 = l - sB;      if (a0 < 0) a0 = -a0;
        int a1 = l - sB - 63; if (a1 < 0) a1 = -a1;
        return a0 > a1 ? a0 : a1;
    };

    auto stage_kvr = [&](int buf, int sB) {
        unsigned kvoff = (unsigned)(buf * KVB * 2);
        unsigned rwoff = (unsigned)(buf * RWB * 2);
        #pragma unroll
        for (int i = 0; i < 2; i++) {
            int ci = kcb + i;
            cpa16(k_a + kvoff + ci*16, Kg + (size_t)(sB + krow)*DH_ + ci*8);
            cpa16(v_a + kvoff + ci*16, Vg + (size_t)(sB + krow)*DH_ + ci*8);
        }
        int e_lo8 = (1023 - admax(rl, sB)) & ~7;
        #pragma unroll
        for (int i = 0; i < 5; i++) {
            int ci = rcb + i;
            cpa16(r_a + rwoff + ci*16, Rrow + e_lo8 + ci*8);
        }
        cpa_commit();
    };

    {   // stage Q (once) + tile 0 into buffer 0
        #pragma unroll
        for (int i = 0; i < 4; i++) {
            int ci = qcb + i;
            cpa16(q_a + ci*16, Qg + (size_t)(lBase + qrow)*DH_ + ci*8);
        }
        stage_kvr(0, 0);
    }

    const int lr8 = lane & 7;
    unsigned aQ = scvta(Qh) +
        (unsigned)(((warp*16 + (lane & 15))*72 + ((lane >> 4)*8)) * 2);
    unsigned bK0 = scvta(Kh) +
        (unsigned)(((lr8 + ((lane & 16) ? 8 : 0))*72 + ((lane & 8) ? 8 : 0)) * 2);
    unsigned bV0 = scvta(Vh) +
        (unsigned)(((lane & 15)*72 + (lane >> 4)*8) * 2);

    const unsigned ONES = 0x3C003C00u;
    float lsum[4] = {0.f, 0.f, 0.f, 0.f};
    float O[8][4] = {};

    const int lg0 = lBase + rA, lg1 = lg0 + 8;

    for (int it = 0; it < 16; it++) {
        const int sBase = it * 64;
        const int buf = it & 1;
        const int base0 = 1023 - ((1023 - admax(lg0, sBase)) & ~7);
        const int base1 = 1023 - ((1023 - admax(lg1, sBase)) & ~7);

        cpa_wait<0>();
        __syncthreads();                                    // tile `it` staged

        if (it + 1 < 16)                                    // overlap: stage i+1
            stage_kvr(buf ^ 1, sBase + 64);

        const unsigned kvoff = (unsigned)(buf * KVB * 2);
        const __half* Rb = Rw + buf * RWB;

        // ---- sf init: gather bias from staged windows (LDS) ----
        float sf[8][4];
        #pragma unroll
        for (int j = 0; j < 8; j++) {
            int c0 = sBase + j*8 + 2*tg;
            #pragma unroll
            for (int q = 0; q < 4; q++) {
                int col  = c0 + (q & 1);
                int lg   = (q < 2) ? lg0 : lg1;
                int rloc = (q < 2) ? rA  : rA + 8;
                int base = (q < 2) ? base0 : base1;
                int d = lg - col; int ad = d < 0 ? -d : d;
                unsigned short hv = *(const unsigned short*)&Rb[rloc*80 + (base - ad)];
                sf[j][q] = __bfloat162float(*(const __nv_bfloat16*)&hv);
            }
        }

        // ---- S GEMM (fp16, accumulates onto bias) ----
        #pragma unroll
        for (int k0 = 0; k0 < 64; k0 += 16) {
            unsigned a0, a1, a2, a3;
            ldsm4(a0, a1, a2, a3, aQ + (unsigned)(k0*2));
            #pragma unroll
            for (int jp = 0; jp < 4; jp++) {
                unsigned b0, b1, b2, b3;
                ldsm4(b0, b1, b2, b3, bK0 + kvoff + (unsigned)((jp*16*72 + k0) * 2));
                mma16h(sf[jp*2],   a0, a1, a2, a3, b0, b1);
                mma16h(sf[jp*2+1], a0, a1, a2, a3, b2, b3);
            }
        }

        // ---- fp16 softmax tail + PV ----
        #pragma unroll
        for (int j2 = 0; j2 < 4; j2++) {
            const int jb0 = 2*j2, jb1 = 2*j2 + 1;
            unsigned a0 = ex2h2(sf[jb0][0], sf[jb0][1]);
            unsigned a1 = ex2h2(sf[jb0][2], sf[jb0][3]);
            unsigned a2 = ex2h2(sf[jb1][0], sf[jb1][1]);
            unsigned a3 = ex2h2(sf[jb1][2], sf[jb1][3]);
            mma16h(lsum, a0, a1, a2, a3, ONES, ONES);
            #pragma unroll
            for (int jp = 0; jp < 4; jp++) {
                unsigned b0, b1, b2, b3;
                ldsm4t(b0, b1, b2, b3, bV0 + kvoff + (unsigned)((j2*16*72 + jp*16) * 2));
                mma16h(O[jp*2],   a0, a1, a2, a3, b0, b1);
                mma16h(O[jp*2+1], a0, a1, a2, a3, b2, b3);
            }
        }
        // no trailing sync: next iteration's top sync (after wait) protects
        // buffer reuse — stage of tile it+2 into `buf` is issued only after
        // all warps passed the top sync of it+1, i.e. finished reading `buf`.
    }

    // normalize + write ctx
    const float i0 = 1.0f / lsum[0], i1 = 1.0f / lsum[2];
    const int b = bh >> 3, hh = bh & 7;
    #pragma unroll
    for (int j = 0; j < 8; j++) {
        int dh = j*8 + 2*tg;
        size_t base0 = ((size_t)(b*L_ + lBase + rA))*D_ + hh*DH_ + dh;
        size_t base1 = ((size_t)(b*L_ + lBase + rA + 8))*D_ + hh*DH_ + dh;
        *(float2*)(g_Ctx + base0) = make_float2(__uint_as_float(f2tf(O[j][0]*i0)),
                                                __uint_as_float(f2tf(O[j][1]*i0)));
        *(float2*)(g_Ctx + base1) = make_float2(__uint_as_float(f2tf(O[j][2]*i1)),
                                                __uint_as_float(f2tf(O[j][3]*i1)));
    }
}

// ---------------------------------------------------------------------------
// Kernel: out = Ctx @ Wo^T + bo
// ---------------------------------------------------------------------------
__global__ void __launch_bounds__(256, 2) out_kernel(
    const float* __restrict__ bo, float* __restrict__ out)
{
    extern __shared__ unsigned smq[];
    unsigned* As = smq;
    unsigned* Bs = smq + 3*128*36;
    const int mBase = blockIdx.x * 128, nBase = blockIdx.y * 128;
    float C[2][8][4] = {};
    gemm_body(g_Ctx, g_Wo, mBase, nBase, As, Bs, C);

    const int t = threadIdx.x, lane = t & 31, warp = t >> 5;
    const int g = lane >> 2, tg = lane & 3;
    const int wm = warp >> 1, wn = warp & 1;
    #pragma unroll
    for (int mi = 0; mi < 2; mi++) {
        #pragma unroll
        for (int j = 0; j < 8; j++) {
            int n = nBase + wn*64 + j*8 + 2*tg;
            float2 bias = *(const float2*)(bo + n);
            #pragma unroll
            for (int hh = 0; hh < 2; hh++) {
                int m = mBase + wm*32 + mi*16 + g + 8*hh;
                float2 v = make_float2(C[mi][j][hh*2] + bias.x, C[mi][j][hh*2+1] + bias.y);
                *(float2*)(out + (size_t)m*D_ + n) = v;
            }
        }
    }
}

// ---------------------------------------------------------------------------
extern "C" void kernel_launch(void* const* d_in, const int* in_sizes, int n_in,
                              void* d_out, int out_size)
{
    const float* x  = (const float*)d_in[0];
    const float* Wq = (const float*)d_in[1];
    const float* Wk = (const float*)d_in[2];
    const float* Wv = (const float*)d_in[3];
    const float* We = (const float*)d_in[4];
    const float* Wo = (const float*)d_in[5];
    const float* bo = (const float*)d_in[6];
    float* out = (float*)d_out;

    const int gemm_smem = 2 * 3 * 128 * 36 * (int)sizeof(unsigned);      // 110592
    const int rel_smem  = 2 * 128 * 72 * (int)sizeof(__half);            // 36864
    const int attn_smem = (128*72 + 2*64*72 + 2*64*72 + 2*128*80)
                          * (int)sizeof(__half);                         // 96256
    cudaFuncSetAttribute(qkv_kernel,  cudaFuncAttributeMaxDynamicSharedMemorySize, gemm_smem);
    cudaFuncSetAttribute(rel_kernel,  cudaFuncAttributeMaxDynamicSharedMemorySize, rel_smem);
    cudaFuncSetAttribute(attn_kernel, cudaFuncAttributeMaxDynamicSharedMemorySize, attn_smem);
    cudaFuncSetAttribute(out_kernel,  cudaFuncAttributeMaxDynamicSharedMemorySize, gemm_smem);

    const int prep_total = XN_ + 4*WN_ + L_*DH_;
    prep_kernel<<<(prep_total/4 + 255)/256, 256>>>(x, Wq, Wk, Wv, Wo, We);

    qkv_kernel<<<dim3(M_/128, D_/128, 3), 256, gemm_smem>>>();
    rel_kernel<<<dim3(L_/128, L_/128, BH_), 256, rel_smem>>>();
    attn_kernel<<<dim3(L_/128, BH_), 256, attn_smem>>>();
    out_kernel<<<dim3(M_/128, D_/128), 256, gemm_smem>>>(bo, out);
}

// round 12
// speedup vs baseline: 2.0673x; 1.1623x over previous
#include <cuda_runtime.h>
#include <cuda_fp16.h>
#include <math.h>

#define B_  8
#define L_  1024
#define D_  512
#define H_  8
#define DH_ 64
#define M_  (B_*L_)     // 8192
#define BH_ (B_*H_)     // 64

// Scratch (device globals: allocation-free kernel_launch per harness rules)
__device__ __align__(16) __half g_Qh[BH_*L_*DH_];  // fp16, 0.125*log2e-scaled
__device__ __align__(16) __half g_Kh[BH_*L_*DH_];
__device__ __align__(16) __half g_Vh[BH_*L_*DH_];
__device__ __align__(16) __half g_Ctxh[M_*D_];     // fp16, (b,l,D)
__device__ __align__(16) __half g_xh[M_*D_];       // fp16 inputs
__device__ __align__(16) __half g_Wqh[D_*D_];
__device__ __align__(16) __half g_Wkh[D_*D_];
__device__ __align__(16) __half g_Wvh[D_*D_];
__device__ __align__(16) __half g_Woh[D_*D_];
__device__ __align__(16) __half g_Weh[L_*DH_];
__device__ __align__(16) __half g_R[(size_t)BH_*L_*L_ + 128]; // bias (log2 domain), padded

// ---------------------------------------------------------------------------
// helpers
// ---------------------------------------------------------------------------
__device__ __forceinline__ void mma16h(float* c,
    unsigned a0, unsigned a1, unsigned a2, unsigned a3,
    unsigned b0, unsigned b1)
{
    asm volatile(
        "mma.sync.aligned.m16n8k16.row.col.f32.f16.f16.f32 "
        "{%0,%1,%2,%3},{%4,%5,%6,%7},{%8,%9},{%0,%1,%2,%3};"
        : "+f"(c[0]), "+f"(c[1]), "+f"(c[2]), "+f"(c[3])
        : "r"(a0), "r"(a1), "r"(a2), "r"(a3), "r"(b0), "r"(b1));
}
__device__ __forceinline__ void ldsm4(unsigned& r0, unsigned& r1,
                                      unsigned& r2, unsigned& r3, unsigned addr)
{
    asm volatile("ldmatrix.sync.aligned.m8n8.x4.shared.b16 {%0,%1,%2,%3}, [%4];"
        : "=r"(r0), "=r"(r1), "=r"(r2), "=r"(r3) : "r"(addr));
}
__device__ __forceinline__ void ldsm4t(unsigned& r0, unsigned& r1,
                                       unsigned& r2, unsigned& r3, unsigned addr)
{
    asm volatile("ldmatrix.sync.aligned.m8n8.x4.trans.shared.b16 {%0,%1,%2,%3}, [%4];"
        : "=r"(r0), "=r"(r1), "=r"(r2), "=r"(r3) : "r"(addr));
}
__device__ __forceinline__ unsigned ex2h2(float lo, float hi) {
    unsigned p;
    asm("cvt.rn.f16x2.f32 %0, %1, %2;" : "=r"(p) : "f"(hi), "f"(lo));
    asm("ex2.approx.f16x2 %0, %0;" : "+r"(p));
    return p;
}
__device__ __forceinline__ unsigned scvta(const void* p) {
    return (unsigned)__cvta_generic_to_shared(p);
}
__device__ __forceinline__ void cpa16(unsigned dst, const void* src) {
    asm volatile("cp.async.cg.shared.global [%0], [%1], 16;" :: "r"(dst), "l"(src));
}
__device__ __forceinline__ void cpa_commit() {
    asm volatile("cp.async.commit_group;");
}
template<int N> __device__ __forceinline__ void cpa_wait() {
    asm volatile("cp.async.wait_group %0;" :: "n"(N));
}

// ---------------------------------------------------------------------------
// Prep: ONE launch converting all inputs to fp16
// ---------------------------------------------------------------------------
#define XN_ (M_*D_)
#define WN_ (D_*D_)
__global__ void __launch_bounds__(256) prep_kernel(
    const float* __restrict__ x,  const float* __restrict__ Wq,
    const float* __restrict__ Wk, const float* __restrict__ Wv,
    const float* __restrict__ Wo, const float* __restrict__ We)
{
    int i = (blockIdx.x * 256 + threadIdx.x) * 4;
    if (i >= XN_ + 4*WN_ + L_*DH_) return;
    const float* s; __half* d;
    if      (i < XN_)          { s = x  + i;               d = g_xh  + i; }
    else if (i < XN_ + WN_)    { s = Wq + i - XN_;         d = g_Wqh + i - XN_; }
    else if (i < XN_ + 2*WN_)  { s = Wk + i - XN_ - WN_;   d = g_Wkh + i - XN_ - WN_; }
    else if (i < XN_ + 3*WN_)  { s = Wv + i - XN_ - 2*WN_; d = g_Wvh + i - XN_ - 2*WN_; }
    else if (i < XN_ + 4*WN_)  { s = Wo + i - XN_ - 3*WN_; d = g_Woh + i - XN_ - 3*WN_; }
    else                       { s = We + i - XN_ - 4*WN_; d = g_Weh + i - XN_ - 4*WN_; }
    float4 v = *(const float4*)s;
    *(__half2*)(d)     = __floats2half2_rn(v.x, v.y);
    *(__half2*)(d + 2) = __floats2half2_rn(v.z, v.w);
}

// ---------------------------------------------------------------------------
// Dense fp16 GEMM body (K=512): C(128x128) = A * W^T, fp32 accum.
// 3-stage cp.async (k-chunks of 32), ldmatrix frags, pitch 40 halves
// (80B: rows hit distinct 16B slots mod 128 -> LDSM conflict-free).
// ---------------------------------------------------------------------------
__device__ __forceinline__ void gemm_body_h(
    const __half* __restrict__ A, const __half* __restrict__ W,
    int mBase, int nBase, __half* As, __half* Bs, float C[2][8][4])
{
    const int t = threadIdx.x, lane = t & 31, warp = t >> 5;
    const int wm = warp >> 1, wn = warp & 1;
    const int srow = t >> 1, sc = (t & 1) * 2;
    const int BUF = 128 * 40;   // halves per buffer

    unsigned a_a = scvta(As) + (unsigned)(srow * 80);
    unsigned b_a = scvta(Bs) + (unsigned)(srow * 80);

    auto stage = [&](int buf, int k0) {
        unsigned off = (unsigned)(buf * BUF * 2);
        #pragma unroll
        for (int i = 0; i < 2; i++) {
            int ci = sc + i;
            cpa16(a_a + off + ci*16, A + (size_t)(mBase + srow) * D_ + k0 + ci*8);
            cpa16(b_a + off + ci*16, W + (size_t)(nBase + srow) * D_ + k0 + ci*8);
        }
        cpa_commit();
    };

    const int lr8 = lane & 7;
    unsigned aAddr = scvta(As) +
        (unsigned)(((wm*32 + (lane & 15))*40 + (lane >> 4)*8) * 2);
    unsigned bAddr = scvta(Bs) +
        (unsigned)(((wn*64 + lr8 + ((lane & 16) ? 8 : 0))*40 + ((lane & 8) ? 8 : 0)) * 2);

    stage(0, 0);
    stage(1, 32);
    int cb = 0, nb = 2, nk = 64;
    for (int it = 0; it < 16; it++) {
        if (it == 15) cpa_wait<0>(); else cpa_wait<1>();
        __syncthreads();
        if (it + 2 < 16) {
            stage(nb, nk);
            nk += 32;
            nb = (nb == 2) ? 0 : nb + 1;
        }
        const unsigned bo = (unsigned)(cb * BUF * 2);
        #pragma unroll
        for (int kk = 0; kk < 32; kk += 16) {
            unsigned a[2][4];
            #pragma unroll
            for (int mi = 0; mi < 2; mi++)
                ldsm4(a[mi][0], a[mi][1], a[mi][2], a[mi][3],
                      aAddr + bo + (unsigned)((mi*16*40 + kk) * 2));
            #pragma unroll
            for (int jp = 0; jp < 4; jp++) {
                unsigned b0, b1, b2, b3;
                ldsm4(b0, b1, b2, b3, bAddr + bo + (unsigned)((jp*16*40 + kk) * 2));
                mma16h(C[0][jp*2],   a[0][0], a[0][1], a[0][2], a[0][3], b0, b1);
                mma16h(C[0][jp*2+1], a[0][0], a[0][1], a[0][2], a[0][3], b2, b3);
                mma16h(C[1][jp*2],   a[1][0], a[1][1], a[1][2], a[1][3], b0, b1);
                mma16h(C[1][jp*2+1], a[1][0], a[1][1], a[1][2], a[1][3], b2, b3);
            }
        }
        cb = (cb == 2) ? 0 : cb + 1;
    }
}

// ---------------------------------------------------------------------------
// Kernel: QKV projections -> fp16 (b,h,l,dh). Q scaled by 0.125*log2(e).
// ---------------------------------------------------------------------------
__global__ void __launch_bounds__(256, 2) qkv_kernel()
{
    extern __shared__ __half smqh[];
    __half* As = smqh;
    __half* Bs = smqh + 3*128*40;
    const __half* W = (blockIdx.z == 0) ? g_Wqh : (blockIdx.z == 1) ? g_Wkh : g_Wvh;
    __half* dst     = (blockIdx.z == 0) ? g_Qh  : (blockIdx.z == 1) ? g_Kh  : g_Vh;
    const float scale = (blockIdx.z == 0) ? 0.125f * 1.4426950408889634f : 1.0f;
    const int mBase = blockIdx.x * 128, nBase = blockIdx.y * 128;
    float C[2][8][4] = {};
    gemm_body_h(g_xh, W, mBase, nBase, As, Bs, C);

    const int t = threadIdx.x, lane = t & 31, warp = t >> 5;
    const int g = lane >> 2, tg = lane & 3;
    const int wm = warp >> 1, wn = warp & 1;
    #pragma unroll
    for (int mi = 0; mi < 2; mi++) {
        #pragma unroll
        for (int j = 0; j < 8; j++) {
            int n = nBase + wn*64 + j*8 + 2*tg;
            int h = n >> 6, dh = n & 63;
            #pragma unroll
            for (int hh = 0; hh < 2; hh++) {
                int m = mBase + wm*32 + mi*16 + g + 8*hh;
                int b = m >> 10, l = m & (L_-1);
                __half2 v = __floats2half2_rn(C[mi][j][hh*2]*scale, C[mi][j][hh*2+1]*scale);
                *(__half2*)(dst + ((size_t)((b*H_+h)*L_ + l))*DH_ + dh) = v;
            }
        }
    }
}

// ---------------------------------------------------------------------------
// Kernel: R[bh][l][e] = Qh[bh,l,:].Weh[e,:] (fp16 mma, K=64), fp16 output
// ---------------------------------------------------------------------------
__global__ void __launch_bounds__(256, 2) rel_kernel()
{
    extern __shared__ __half smr[];
    __half* Ah = smr;               // 128 x 72 halves
    __half* Bh = smr + 128*72;
    const int bh = blockIdx.z;
    const int mBase = blockIdx.x * 128, nBase = blockIdx.y * 128;
    const __half* A  = g_Qh + (size_t)bh * L_ * DH_;
    const __half* Wb = g_Weh;

    const int t = threadIdx.x, lane = t & 31, warp = t >> 5;
    const int wm = warp >> 1, wn = warp & 1;

    const int lr2 = t >> 1, lc2 = (t & 1) * 4;
    unsigned a_a = scvta(Ah) + (unsigned)(lr2*144);
    unsigned b_a = scvta(Bh) + (unsigned)(lr2*144);
    #pragma unroll
    for (int i = 0; i < 4; i++) {
        int ci = lc2 + i;
        cpa16(a_a + ci*16, A  + (size_t)(mBase + lr2) * DH_ + ci*8);
        cpa16(b_a + ci*16, Wb + (size_t)(nBase + lr2) * DH_ + ci*8);
    }
    cpa_commit(); cpa_wait<0>();
    __syncthreads();

    const int lr8 = lane & 7;
    unsigned aAddr = scvta(Ah) +
        (unsigned)(((wm*32 + (lane & 15))*72 + ((lane >> 4)*8)) * 2);
    unsigned bAddr = scvta(Bh) +
        (unsigned)(((wn*64 + lr8 + ((lane & 16) ? 8 : 0))*72 + ((lane & 8) ? 8 : 0)) * 2);

    float C[2][8][4] = {};
    #pragma unroll
    for (int k0 = 0; k0 < 64; k0 += 16) {
        unsigned a[2][4];
        #pragma unroll
        for (int mi = 0; mi < 2; mi++)
            ldsm4(a[mi][0], a[mi][1], a[mi][2], a[mi][3],
                  aAddr + (unsigned)((mi*16*72 + k0) * 2));
        #pragma unroll
        for (int jp = 0; jp < 4; jp++) {
            unsigned b0, b1, b2, b3;
            ldsm4(b0, b1, b2, b3, bAddr + (unsigned)((jp*16*72 + k0) * 2));
            mma16h(C[0][jp*2],   a[0][0], a[0][1], a[0][2], a[0][3], b0, b1);
            mma16h(C[0][jp*2+1], a[0][0], a[0][1], a[0][2], a[0][3], b2, b3);
            mma16h(C[1][jp*2],   a[1][0], a[1][1], a[1][2], a[1][3], b0, b1);
            mma16h(C[1][jp*2+1], a[1][0], a[1][1], a[1][2], a[1][3], b2, b3);
        }
    }

    const int g = lane >> 2, tg = lane & 3;
    __half* Rb = g_R + (size_t)bh * L_ * L_;
    #pragma unroll
    for (int mi = 0; mi < 2; mi++) {
        #pragma unroll
        for (int j = 0; j < 8; j++) {
            int n = nBase + wn*64 + j*8 + 2*tg;
            #pragma unroll
            for (int hh = 0; hh < 2; hh++) {
                int m = mBase + wm*32 + mi*16 + g + 8*hh;
                __half2 v = __floats2half2_rn(C[mi][j][hh*2], C[mi][j][hh*2+1]);
                *(__half2*)(Rb + (size_t)m*L_ + n) = v;
            }
        }
    }
}

// ---------------------------------------------------------------------------
// Kernel: flash attention. 256 threads, 128-row q-tiles, double-buffered
// K/V/bias staging, all-fp16 mma. Bias gather: zero-ALU immediate-offset
// LDS for the 14/16 off-diagonal tiles (e is linear in s), abs path for
// the 2 diagonal-crossing tiles.
// ---------------------------------------------------------------------------
__global__ void __launch_bounds__(256, 2) attn_kernel()
{
    extern __shared__ __half sma[];
    __half* Qh = sma;                    // 128 x 72
    __half* Kh = Qh + 128*72;            // 2 buf x 64 x 72
    __half* Vh = Kh + 2*64*72;           // 2 buf x 64 x 72
    __half* Rw = Vh + 2*64*72;           // 2 buf x 128 x 80

    const int KVB = 64*72;
    const int RWB = 128*80;

    const int bh = blockIdx.y, lBase = blockIdx.x * 128;
    const __half* __restrict__ Qg = g_Qh + (size_t)bh * L_ * DH_;
    const __half* __restrict__ Kg = g_Kh + (size_t)bh * L_ * DH_;
    const __half* __restrict__ Vg = g_Vh + (size_t)bh * L_ * DH_;
    const __half* __restrict__ Rg = g_R + ((size_t)bh << 20);

    const int t = threadIdx.x, lane = t & 31, warp = t >> 5;
    const int g = lane >> 2, tg = lane & 3;
    const int rA = warp*16 + g;          // 0..127

    const int qrow = t >> 1, qcb = (t & 1) * 4;
    const int krow = t & 63, kcb = (t >> 6) * 2;
    const int rrow = t >> 1, rcb = (t & 1) * 5;
    unsigned q_a = scvta(Qh) + (unsigned)(qrow*144);
    unsigned k_a = scvta(Kh) + (unsigned)(krow*144);
    unsigned v_a = scvta(Vh) + (unsigned)(krow*144);
    unsigned r_a = scvta(Rw) + (unsigned)(rrow*160);
    const int rl = lBase + rrow;
    const __half* Rrow = Rg + ((size_t)rl << 10);

    auto admax = [](int l, int sB) {
        int a0 = l - sB;      if (a0 < 0) a0 = -a0;
        int a1 = l - sB - 63; if (a1 < 0) a1 = -a1;
        return a0 > a1 ? a0 : a1;
    };

    auto stage_kvr = [&](int buf, int sB) {
        unsigned kvoff = (unsigned)(buf * KVB * 2);
        unsigned rwoff = (unsigned)(buf * RWB * 2);
        #pragma unroll
        for (int i = 0; i < 2; i++) {
            int ci = kcb + i;
            cpa16(k_a + kvoff + ci*16, Kg + (size_t)(sB + krow)*DH_ + ci*8);
            cpa16(v_a + kvoff + ci*16, Vg + (size_t)(sB + krow)*DH_ + ci*8);
        }
        int e_lo8 = (1023 - admax(rl, sB)) & ~7;
        #pragma unroll
        for (int i = 0; i < 5; i++) {
            int ci = rcb + i;
            cpa16(r_a + rwoff + ci*16, Rrow + e_lo8 + ci*8);
        }
        cpa_commit();
    };

    {   // stage Q (once) + tile 0 into buffer 0
        #pragma unroll
        for (int i = 0; i < 4; i++) {
            int ci = qcb + i;
            cpa16(q_a + ci*16, Qg + (size_t)(lBase + qrow)*DH_ + ci*8);
        }
        stage_kvr(0, 0);
    }

    const int lr8 = lane & 7;
    unsigned aQ = scvta(Qh) +
        (unsigned)(((warp*16 + (lane & 15))*72 + ((lane >> 4)*8)) * 2);
    unsigned bK0 = scvta(Kh) +
        (unsigned)(((lr8 + ((lane & 16) ? 8 : 0))*72 + ((lane & 8) ? 8 : 0)) * 2);
    unsigned bV0 = scvta(Vh) +
        (unsigned)(((lane & 15)*72 + (lane >> 4)*8) * 2);

    const unsigned ONES = 0x3C003C00u;
    float lsum[4] = {0.f, 0.f, 0.f, 0.f};
    float O[8][4] = {};

    const int lg0 = lBase + rA, lg1 = lg0 + 8;

    for (int it = 0; it < 16; it++) {
        const int sBase = it * 64;
        const int buf = it & 1;

        cpa_wait<0>();
        __syncthreads();                                    // tile `it` staged

        if (it + 1 < 16)                                    // overlap: stage i+1
            stage_kvr(buf ^ 1, sBase + 64);

        const unsigned kvoff = (unsigned)(buf * KVB * 2);
        const __half* Rb = Rw + buf * RWB;

        // ---- sf init: bias gather from staged windows ----
        float sf[8][4];
        if (lBase >= sBase + 64) {
            // pure lower (l > s): idx = (w&7) + cc, w = 1023 - l + sBase
            const __half* p0 = Rb + rA*80     + ((1023 - lg0 + sBase) & 7) + 2*tg;
            const __half* p1 = Rb + (rA+8)*80 + ((1023 - lg1 + sBase) & 7) + 2*tg;
            #pragma unroll
            for (int j = 0; j < 8; j++) {
                sf[j][0] = __half2float(p0[j*8]);
                sf[j][1] = __half2float(p0[j*8 + 1]);
                sf[j][2] = __half2float(p1[j*8]);
                sf[j][3] = __half2float(p1[j*8 + 1]);
            }
        } else if (sBase >= lBase + 128) {
            // pure upper (s > l): idx = (u&7) + 63 - cc, u = 960 - sBase + l
            const __half* p0 = Rb + rA*80     + ((960 - sBase + lg0) & 7) + 63 - 2*tg;
            const __half* p1 = Rb + (rA+8)*80 + ((960 - sBase + lg1) & 7) + 63 - 2*tg;
            #pragma unroll
            for (int j = 0; j < 8; j++) {
                sf[j][0] = __half2float(p0[-(j*8)]);
                sf[j][1] = __half2float(p0[-(j*8) - 1]);
                sf[j][2] = __half2float(p1[-(j*8)]);
                sf[j][3] = __half2float(p1[-(j*8) - 1]);
            }
        } else {
            // diagonal-crossing tiles (2 of 16): generic abs path
            const int base0 = 1023 - ((1023 - admax(lg0, sBase)) & ~7);
            const int base1 = 1023 - ((1023 - admax(lg1, sBase)) & ~7);
            #pragma unroll
            for (int j = 0; j < 8; j++) {
                int c0 = sBase + j*8 + 2*tg;
                #pragma unroll
                for (int q = 0; q < 4; q++) {
                    int col  = c0 + (q & 1);
                    int lg   = (q < 2) ? lg0 : lg1;
                    int rloc = (q < 2) ? rA  : rA + 8;
                    int base = (q < 2) ? base0 : base1;
                    int d = lg - col; int ad = d < 0 ? -d : d;
                    sf[j][q] = __half2float(Rb[rloc*80 + base - ad]);
                }
            }
        }

        // ---- S GEMM (fp16, accumulates onto bias) ----
        #pragma unroll
        for (int k0 = 0; k0 < 64; k0 += 16) {
            unsigned a0, a1, a2, a3;
            ldsm4(a0, a1, a2, a3, aQ + (unsigned)(k0*2));
            #pragma unroll
            for (int jp = 0; jp < 4; jp++) {
                unsigned b0, b1, b2, b3;
                ldsm4(b0, b1, b2, b3, bK0 + kvoff + (unsigned)((jp*16*72 + k0) * 2));
                mma16h(sf[jp*2],   a0, a1, a2, a3, b0, b1);
                mma16h(sf[jp*2+1], a0, a1, a2, a3, b2, b3);
            }
        }

        // ---- fp16 softmax tail + PV ----
        #pragma unroll
        for (int j2 = 0; j2 < 4; j2++) {
            const int jb0 = 2*j2, jb1 = 2*j2 + 1;
            unsigned a0 = ex2h2(sf[jb0][0], sf[jb0][1]);
            unsigned a1 = ex2h2(sf[jb0][2], sf[jb0][3]);
            unsigned a2 = ex2h2(sf[jb1][0], sf[jb1][1]);
            unsigned a3 = ex2h2(sf[jb1][2], sf[jb1][3]);
            mma16h(lsum, a0, a1, a2, a3, ONES, ONES);
            #pragma unroll
            for (int jp = 0; jp < 4; jp++) {
                unsigned b0, b1, b2, b3;
                ldsm4t(b0, b1, b2, b3, bV0 + kvoff + (unsigned)((j2*16*72 + jp*16) * 2));
                mma16h(O[jp*2],   a0, a1, a2, a3, b0, b1);
                mma16h(O[jp*2+1], a0, a1, a2, a3, b2, b3);
            }
        }
        // buffer reuse protected by next iteration's top sync
    }

    // normalize + write ctx (fp16)
    const float i0 = 1.0f / lsum[0], i1 = 1.0f / lsum[2];
    const int b = bh >> 3, hh = bh & 7;
    #pragma unroll
    for (int j = 0; j < 8; j++) {
        int dh = j*8 + 2*tg;
        size_t base0 = ((size_t)(b*L_ + lBase + rA))*D_ + hh*DH_ + dh;
        size_t base1 = ((size_t)(b*L_ + lBase + rA + 8))*D_ + hh*DH_ + dh;
        *(__half2*)(g_Ctxh + base0) = __floats2half2_rn(O[j][0]*i0, O[j][1]*i0);
        *(__half2*)(g_Ctxh + base1) = __floats2half2_rn(O[j][2]*i1, O[j][3]*i1);
    }
}

// ---------------------------------------------------------------------------
// Kernel: out = Ctx @ Wo^T + bo   (fp16 GEMM, fp32 out)
// ---------------------------------------------------------------------------
__global__ void __launch_bounds__(256, 2) out_kernel(
    const float* __restrict__ bo, float* __restrict__ out)
{
    extern __shared__ __half smqh[];
    __half* As = smqh;
    __half* Bs = smqh + 3*128*40;
    const int mBase = blockIdx.x * 128, nBase = blockIdx.y * 128;
    float C[2][8][4] = {};
    gemm_body_h(g_Ctxh, g_Woh, mBase, nBase, As, Bs, C);

    const int t = threadIdx.x, lane = t & 31, warp = t >> 5;
    const int g = lane >> 2, tg = lane & 3;
    const int wm = warp >> 1, wn = warp & 1;
    #pragma unroll
    for (int mi = 0; mi < 2; mi++) {
        #pragma unroll
        for (int j = 0; j < 8; j++) {
            int n = nBase + wn*64 + j*8 + 2*tg;
            float2 bias = *(const float2*)(bo + n);
            #pragma unroll
            for (int hh = 0; hh < 2; hh++) {
                int m = mBase + wm*32 + mi*16 + g + 8*hh;
                float2 v = make_float2(C[mi][j][hh*2] + bias.x, C[mi][j][hh*2+1] + bias.y);
                *(float2*)(out + (size_t)m*D_ + n) = v;
            }
        }
    }
}

// ---------------------------------------------------------------------------
extern "C" void kernel_launch(void* const* d_in, const int* in_sizes, int n_in,
                              void* d_out, int out_size)
{
    const float* x  = (const float*)d_in[0];
    const float* Wq = (const float*)d_in[1];
    const float* Wk = (const float*)d_in[2];
    const float* Wv = (const float*)d_in[3];
    const float* We = (const float*)d_in[4];
    const float* Wo = (const float*)d_in[5];
    const float* bo = (const float*)d_in[6];
    float* out = (float*)d_out;

    const int gemm_smem = 2 * 3 * 128 * 40 * (int)sizeof(__half);        // 61440
    const int rel_smem  = 2 * 128 * 72 * (int)sizeof(__half);            // 36864
    const int attn_smem = (128*72 + 2*64*72 + 2*64*72 + 2*128*80)
                          * (int)sizeof(__half);                         // 96256
    cudaFuncSetAttribute(qkv_kernel,  cudaFuncAttributeMaxDynamicSharedMemorySize, gemm_smem);
    cudaFuncSetAttribute(rel_kernel,  cudaFuncAttributeMaxDynamicSharedMemorySize, rel_smem);
    cudaFuncSetAttribute(attn_kernel, cudaFuncAttributeMaxDynamicSharedMemorySize, attn_smem);
    cudaFuncSetAttribute(out_kernel,  cudaFuncAttributeMaxDynamicSharedMemorySize, gemm_smem);

    const int prep_total = XN_ + 4*WN_ + L_*DH_;
    prep_kernel<<<(prep_total/4 + 255)/256, 256>>>(x, Wq, Wk, Wv, Wo, We);

    qkv_kernel<<<dim3(M_/128, D_/128, 3), 256, gemm_smem>>>();
    rel_kernel<<<dim3(L_/128, L_/128, BH_), 256, rel_smem>>>();
    attn_kernel<<<dim3(L_/128, BH_), 256, attn_smem>>>();
    out_kernel<<<dim3(M_/128, D_/128), 256, gemm_smem>>>(bo, out);
}